// round 11
// baseline (speedup 1.0000x reference)
#include <cuda_runtime.h>
#include <cuda_bf16.h>
#include <cuda_fp16.h>
#include <cstdint>

#define NMAX 100000
#define EMAX 1600000
#define INC  128
#define HID  128
#define OUTC 64
#define EPS  1e-5f
#define CSRB 98   // blocks for CSR-build kernels (98*1024 threads, all resident)

// ---------------- scratch (no allocations allowed) ----------------
__device__ int    g_cnt[NMAX];
__device__ int    g_rowptr[NMAX + 1];
__device__ int    g_fill[NMAX];
__device__ int    g_col[EMAX];
__device__ float  g_dinv[NMAX];
__device__ int    g_bsum[128];
__device__ int    g_gbar[4], g_gflag[4];       // grid-barrier slots
__device__ int    g_ctr1, g_ctr2, g_flag2;
__device__ __half g_h1h[(size_t)NMAX * HID];   // (x@W1)*dinv[row], fp16
__device__ __half g_a1h[(size_t)NMAX * HID];   // aggregated layer-1 (pre-BN), fp16
__device__ __half g_h2h[(size_t)NMAX * OUTC];  // (relu(bn1)@W2)*dinv[row], fp16
__device__ float  g_stats1[4 * HID];           // sum | sq | s | t
__device__ float  g_stats2[4 * OUTC];

// ---------------- helpers ----------------
__device__ __forceinline__ uint32_t smem_u32(const void* p) {
    uint32_t a;
    asm("{ .reg .u64 t; cvta.to.shared.u64 t, %1; cvt.u32.u64 %0, t; }" : "=r"(a) : "l"(p));
    return a;
}
__device__ __forceinline__ void ldmatrix_x4(uint32_t* r, uint32_t addr) {
    asm volatile("ldmatrix.sync.aligned.m8n8.x4.shared.b16 {%0,%1,%2,%3}, [%4];"
                 : "=r"(r[0]), "=r"(r[1]), "=r"(r[2]), "=r"(r[3]) : "r"(addr));
}
__device__ __forceinline__ void mma_bf16(float* c, const uint32_t* a, uint32_t b0, uint32_t b1) {
    asm volatile(
        "mma.sync.aligned.m16n8k16.row.col.f32.bf16.bf16.f32 "
        "{%0,%1,%2,%3}, {%4,%5,%6,%7}, {%8,%9}, {%0,%1,%2,%3};"
        : "+f"(c[0]), "+f"(c[1]), "+f"(c[2]), "+f"(c[3])
        : "r"(a[0]), "r"(a[1]), "r"(a[2]), "r"(a[3]), "r"(b0), "r"(b1));
}
// grid barrier (slot used once per launch; reset cross-kernel)
__device__ __forceinline__ void gridbarrier(int slot, int nblk) {
    __threadfence();
    __syncthreads();
    if (threadIdx.x == 0) {
        if (atomicAdd(&g_gbar[slot], 1) == nblk - 1) atomicExch(&g_gflag[slot], 1);
        else while (atomicAdd(&g_gflag[slot], 0) == 0) { }
    }
    __syncthreads();
    __threadfence();
}

// ---------------- kernel A: zero + count (fused) ----------------
__global__ __launch_bounds__(1024, 1)
void build_a_kernel(const int* __restrict__ dst, int n, int E4) {
    int tid = blockIdx.x * 1024 + threadIdx.x;
    int nthr = gridDim.x * 1024;
    // phase 0: zero counters/stats + reset kernel-B barrier slots & agg counters
    for (int i = tid; i < n; i += nthr) g_cnt[i] = 0;
    if (tid < 4 * HID)  g_stats1[tid] = 0.f;
    if (tid < 4 * OUTC) g_stats2[tid] = 0.f;
    if (tid == 0) {
        g_ctr1 = 0; g_ctr2 = 0; g_flag2 = 0;
        g_gbar[1] = 0; g_gflag[1] = 0;
        g_gbar[2] = 0; g_gflag[2] = 0;
    }
    gridbarrier(0, gridDim.x);
    // phase 1: degree count, 4 edges per thread per iter
    const int4* d4 = (const int4*)dst;
    for (int i = tid; i < E4; i += nthr) {
        int4 d = d4[i];
        atomicAdd(&g_cnt[d.x], 1); atomicAdd(&g_cnt[d.y], 1);
        atomicAdd(&g_cnt[d.z], 1); atomicAdd(&g_cnt[d.w], 1);
    }
}

// ---------------- kernel B: scan + rowptr/dinv + fill (fused) ----------------
__global__ __launch_bounds__(1024, 1)
void build_b_kernel(const int* __restrict__ src, const int* __restrict__ dst,
                    int n, int E4) {
    __shared__ int ws[32];
    int tid = threadIdx.x, lane = tid & 31, w = tid >> 5;
    if (blockIdx.x == 0 && tid == 0) { g_gbar[0] = 0; g_gflag[0] = 0; }  // reset A's slot
    // phase 1: per-block scan of 1024 counts
    int i = blockIdx.x * 1024 + tid;
    int v = (i < n) ? g_cnt[i] : 0;
    int x = v;
    #pragma unroll
    for (int off = 1; off < 32; off <<= 1) {
        int y = __shfl_up_sync(0xffffffffu, x, off);
        if (lane >= off) x += y;
    }
    if (lane == 31) ws[w] = x;
    __syncthreads();
    if (w == 0) {
        int y = ws[lane];
        #pragma unroll
        for (int off = 1; off < 32; off <<= 1) {
            int z = __shfl_up_sync(0xffffffffu, y, off);
            if (lane >= off) y += z;
        }
        ws[lane] = y;
    }
    __syncthreads();
    int incl = x + (w ? ws[w - 1] : 0);
    if (i < n) g_fill[i] = incl - v;
    if (tid == 1023) g_bsum[blockIdx.x] = incl;
    gridbarrier(1, gridDim.x);
    // phase 2: redundant scan of block sums; finalize fill/rowptr/dinv
    __shared__ int excl[128];
    __shared__ int wsum[4];
    int xv = 0, vv = 0;
    if (tid < 128) {
        vv = (tid < (int)gridDim.x) ? g_bsum[tid] : 0;
        xv = vv;
        #pragma unroll
        for (int off = 1; off < 32; off <<= 1) {
            int y = __shfl_up_sync(0xffffffffu, xv, off);
            if (lane >= off) xv += y;
        }
        if (lane == 31) wsum[w] = xv;
    }
    __syncthreads();
    if (tid < 128) {
        int add = 0;
        #pragma unroll
        for (int j = 0; j < 4; j++) if (j < w) add += wsum[j];
        excl[tid] = xv - vv + add;
    }
    __syncthreads();
    int off = excl[blockIdx.x];
    if (i < n) {
        int c = g_cnt[i];
        int ex = g_fill[i] + off;
        g_fill[i] = ex;
        g_rowptr[i + 1] = ex + c;
        g_dinv[i] = rsqrtf((float)(c + 1));
        if (i == 0) g_rowptr[0] = 0;
    }
    gridbarrier(2, gridDim.x);
    // phase 3: CSR fill, 4 edges per thread per iter
    int gtid = blockIdx.x * 1024 + tid;
    int nthr = gridDim.x * 1024;
    const int4* s4 = (const int4*)src;
    const int4* d4 = (const int4*)dst;
    for (int e = gtid; e < E4; e += nthr) {
        int4 s = s4[e];
        int4 d = d4[e];
        g_col[atomicAdd(&g_fill[d.x], 1)] = s.x;
        g_col[atomicAdd(&g_fill[d.y], 1)] = s.y;
        g_col[atomicAdd(&g_fill[d.z], 1)] = s.z;
        g_col[atomicAdd(&g_fill[d.w], 1)] = s.w;
    }
}

// ---------------- HMMA bf16 GEMM ----------------
// A,W split into bf16 hi/lo; D = Ah*Wh + Al*Wh + Ah*Wl (fp32 accum).
// PRE_BN: A is fp16 g_a1h with relu(a*s[k]+t[k]) folded into the load.
// Epilogue scale: DINVC -> rsqrt(cnt+1) from g_cnt; DINV -> g_dinv.
#define ASTR 136
template <int TN, bool PRE_BN, bool DINVC, bool DINV>
__global__ __launch_bounds__(256)
void mmagemm_kernel(const float* __restrict__ Aext, const float* __restrict__ W, int M) {
    extern __shared__ char smem[];
    const uint32_t SM_ST = 0;
    const uint32_t A_HI  = 1024;
    const uint32_t A_LO  = A_HI + 128 * ASTR * 2;
    const uint32_t B_HI  = A_LO + 128 * ASTR * 2;
    const uint32_t B_LO  = B_HI + TN * ASTR * 2;

    uint32_t sb = smem_u32(smem);
    int tid = threadIdx.x, wid = tid >> 5, lane = tid & 31;
    int m0 = blockIdx.x * 128;

    if (PRE_BN && tid < 256) {
        float v = (tid < 128) ? g_stats1[2 * HID + tid] : g_stats1[3 * HID + (tid - 128)];
        *(float*)(smem + SM_ST + tid * 4) = v;
    }

    __half* Cout = PRE_BN ? g_h2h : g_h1h;
    const float* s = (const float*)(smem + SM_ST);
    const float* t = s + 128;
    if (PRE_BN) __syncthreads();

    if (PRE_BN) {
        #pragma unroll
        for (int it = 0; it < 8; ++it) {
            int idx = tid + it * 256;
            int row = idx >> 4;
            int c8  = (idx & 15) * 8;
            uint4 u = make_uint4(0, 0, 0, 0);
            if (m0 + row < M) u = *(const uint4*)&g_a1h[(size_t)(m0 + row) * 128 + c8];
            const __half2* hp = (const __half2*)&u;
            uint32_t off = (uint32_t)row * (ASTR * 2) + (uint32_t)c8 * 2;
            #pragma unroll
            for (int j = 0; j < 4; j++) {
                float2 f = __half22float2(hp[j]);
                int k = c8 + 2 * j;
                f.x = fmaxf(fmaf(f.x, s[k + 0], t[k + 0]), 0.f);
                f.y = fmaxf(fmaf(f.y, s[k + 1], t[k + 1]), 0.f);
                __nv_bfloat162 h = __floats2bfloat162_rn(f.x, f.y);
                __nv_bfloat162 l = __floats2bfloat162_rn(f.x - __bfloat162float(h.x),
                                                         f.y - __bfloat162float(h.y));
                *(__nv_bfloat162*)(smem + A_HI + off + 4 * j) = h;
                *(__nv_bfloat162*)(smem + A_LO + off + 4 * j) = l;
            }
        }
    } else {
        #pragma unroll
        for (int it = 0; it < 16; ++it) {
            int idx = tid + it * 256;
            int row = idx >> 5;
            int col = (idx & 31) << 2;
            float4 v = make_float4(0.f, 0.f, 0.f, 0.f);
            if (m0 + row < M) v = *(const float4*)&Aext[(size_t)(m0 + row) * 128 + col];
            __nv_bfloat162 h01 = __floats2bfloat162_rn(v.x, v.y);
            __nv_bfloat162 h23 = __floats2bfloat162_rn(v.z, v.w);
            __nv_bfloat162 l01 = __floats2bfloat162_rn(v.x - __bfloat162float(h01.x),
                                                       v.y - __bfloat162float(h01.y));
            __nv_bfloat162 l23 = __floats2bfloat162_rn(v.z - __bfloat162float(h23.x),
                                                       v.w - __bfloat162float(h23.y));
            uint32_t off = (uint32_t)row * (ASTR * 2) + (uint32_t)col * 2;
            *(__nv_bfloat162*)(smem + A_HI + off)     = h01;
            *(__nv_bfloat162*)(smem + A_HI + off + 4) = h23;
            *(__nv_bfloat162*)(smem + A_LO + off)     = l01;
            *(__nv_bfloat162*)(smem + A_LO + off + 4) = l23;
        }
    }
    for (int idx = tid; idx < 128 * TN; idx += 256) {
        int k = idx / TN, n = idx % TN;
        float w = W[idx];
        __nv_bfloat16 hi = __float2bfloat16_rn(w);
        __nv_bfloat16 lo = __float2bfloat16_rn(w - __bfloat162float(hi));
        uint32_t off = (uint32_t)n * (ASTR * 2) + (uint32_t)k * 2;
        *(__nv_bfloat16*)(smem + B_HI + off) = hi;
        *(__nv_bfloat16*)(smem + B_LO + off) = lo;
    }
    __syncthreads();

    constexpr int WN   = TN / 2;
    constexpr int NSUB = WN / 8;
    int m_base = (wid & 3) * 32;
    int n_base = (wid >> 2) * WN;
    int g = lane >> 2, tt = lane & 3;

    float acc[2][NSUB][4];
    #pragma unroll
    for (int mi = 0; mi < 2; mi++)
        #pragma unroll
        for (int ni = 0; ni < NSUB; ni++)
            #pragma unroll
            for (int j = 0; j < 4; j++) acc[mi][ni][j] = 0.f;

    uint32_t a_row = (uint32_t)(m_base + (lane & 15));
    uint32_t a_cb  = (uint32_t)((lane >> 4) * 8);

    #pragma unroll
    for (int term = 0; term < 3; ++term) {
        uint32_t Abase = sb + ((term == 1) ? A_LO : A_HI);
        uint32_t Bbase = ((term == 2) ? B_LO : B_HI);
        #pragma unroll
        for (int ks = 0; ks < 8; ++ks) {
            int k0 = ks * 16;
            uint32_t af[2][4];
            #pragma unroll
            for (int mi = 0; mi < 2; mi++) {
                uint32_t addr = Abase + (a_row + mi * 16) * (ASTR * 2) + (a_cb + k0) * 2;
                ldmatrix_x4(af[mi], addr);
            }
            const char* brow = smem + Bbase + (uint32_t)(n_base + g) * (ASTR * 2) + (uint32_t)(k0 + 2 * tt) * 2;
            #pragma unroll
            for (int ni = 0; ni < NSUB; ni++) {
                uint32_t b0 = *(const uint32_t*)(brow + ni * 8 * (ASTR * 2));
                uint32_t b1 = *(const uint32_t*)(brow + ni * 8 * (ASTR * 2) + 16);
                mma_bf16(acc[0][ni], af[0], b0, b1);
                mma_bf16(acc[1][ni], af[1], b0, b1);
            }
        }
    }

    #pragma unroll
    for (int mi = 0; mi < 2; mi++) {
        int r0 = m0 + m_base + mi * 16 + g;
        int r1 = r0 + 8;
        float d0 = 1.f, d1 = 1.f;
        if (DINVC) {
            d0 = (r0 < M) ? rsqrtf((float)(g_cnt[r0] + 1)) : 0.f;
            d1 = (r1 < M) ? rsqrtf((float)(g_cnt[r1] + 1)) : 0.f;
        }
        if (DINV) {
            d0 = (r0 < M) ? g_dinv[r0] : 0.f;
            d1 = (r1 < M) ? g_dinv[r1] : 0.f;
        }
        #pragma unroll
        for (int ni = 0; ni < NSUB; ni++) {
            int col = n_base + ni * 8 + 2 * tt;
            if (r0 < M)
                *(__half2*)&Cout[(size_t)r0 * TN + col] =
                    __floats2half2_rn(acc[mi][ni][0] * d0, acc[mi][ni][1] * d0);
            if (r1 < M)
                *(__half2*)&Cout[(size_t)r1 * TN + col] =
                    __floats2half2_rn(acc[mi][ni][2] * d1, acc[mi][ni][3] * d1);
        }
    }
}

// ---------------- aggregation helpers ----------------
__device__ __forceinline__ float4 h4_to_f4(uint2 u) {
    float2 a = __half22float2(*(__half2*)&u.x);
    float2 b = __half22float2(*(__half2*)&u.y);
    return make_float4(a.x, a.y, b.x, b.y);
}

// ---------------- aggregation, 128 cols; out fp16 a1; fused BN1 params ----------------
__global__ __launch_bounds__(256)
void agg128_kernel(const float* __restrict__ b, const float* __restrict__ gamma,
                   const float* __restrict__ beta, int n, float invN) {
    int gwarp  = (blockIdx.x * blockDim.x + threadIdx.x) >> 5;
    int lane   = threadIdx.x & 31;
    int nwarps = (gridDim.x * blockDim.x) >> 5;
    const uint2* base = (const uint2*)g_h1h;
    float4 bb = ((const float4*)b)[lane];
    float4 sum = make_float4(0, 0, 0, 0), sq = make_float4(0, 0, 0, 0);

    for (int node = gwarp; node < n; node += nwarps) {
        int e0 = g_rowptr[node], e1 = g_rowptr[node + 1];
        float4 acc = h4_to_f4(base[(size_t)node * 32 + lane]);
        int e = e0;
        for (; e + 4 <= e1; e += 4) {
            int i0 = g_col[e], i1 = g_col[e + 1], i2 = g_col[e + 2], i3 = g_col[e + 3];
            float4 v0 = h4_to_f4(base[(size_t)i0 * 32 + lane]);
            float4 v1 = h4_to_f4(base[(size_t)i1 * 32 + lane]);
            float4 v2 = h4_to_f4(base[(size_t)i2 * 32 + lane]);
            float4 v3 = h4_to_f4(base[(size_t)i3 * 32 + lane]);
            acc.x += (v0.x + v1.x) + (v2.x + v3.x);
            acc.y += (v0.y + v1.y) + (v2.y + v3.y);
            acc.z += (v0.z + v1.z) + (v2.z + v3.z);
            acc.w += (v0.w + v1.w) + (v2.w + v3.w);
        }
        for (; e < e1; e++) {
            float4 v = h4_to_f4(base[(size_t)g_col[e] * 32 + lane]);
            acc.x += v.x; acc.y += v.y; acc.z += v.z; acc.w += v.w;
        }
        float d = g_dinv[node];
        float4 o;
        o.x = fmaf(acc.x, d, bb.x); o.y = fmaf(acc.y, d, bb.y);
        o.z = fmaf(acc.z, d, bb.z); o.w = fmaf(acc.w, d, bb.w);
        uint2 st;
        *(__half2*)&st.x = __floats2half2_rn(o.x, o.y);
        *(__half2*)&st.y = __floats2half2_rn(o.z, o.w);
        ((uint2*)g_a1h)[(size_t)node * 32 + lane] = st;
        sum.x += o.x; sum.y += o.y; sum.z += o.z; sum.w += o.w;
        sq.x += o.x * o.x; sq.y += o.y * o.y; sq.z += o.z * o.z; sq.w += o.w * o.w;
    }
    __shared__ float ssum[HID], ssq[HID];
    int t = threadIdx.x;
    if (t < HID) { ssum[t] = 0.f; ssq[t] = 0.f; }
    __syncthreads();
    int c0 = lane * 4;
    atomicAdd(&ssum[c0 + 0], sum.x); atomicAdd(&ssum[c0 + 1], sum.y);
    atomicAdd(&ssum[c0 + 2], sum.z); atomicAdd(&ssum[c0 + 3], sum.w);
    atomicAdd(&ssq[c0 + 0], sq.x);  atomicAdd(&ssq[c0 + 1], sq.y);
    atomicAdd(&ssq[c0 + 2], sq.z);  atomicAdd(&ssq[c0 + 3], sq.w);
    __syncthreads();
    if (t < HID) {
        atomicAdd(&g_stats1[t], ssum[t]);
        atomicAdd(&g_stats1[HID + t], ssq[t]);
    }
    __threadfence();
    __shared__ int isLast;
    __syncthreads();
    if (t == 0) isLast = (atomicAdd(&g_ctr1, 1) == (int)gridDim.x - 1);
    __syncthreads();
    if (isLast && t < HID) {
        float mean = g_stats1[t] * invN;
        float var  = g_stats1[HID + t] * invN - mean * mean;
        float sc = gamma[t] * rsqrtf(var + EPS);
        g_stats1[2 * HID + t] = sc;
        g_stats1[3 * HID + t] = beta[t] - mean * sc;
    }
}

// ---------------- aggregation, 64 cols + fused grid-barrier BN2 apply ----------------
__global__ __launch_bounds__(256, 4)
void agg64_kernel(const float* __restrict__ b, const float* __restrict__ gamma,
                  const float* __restrict__ beta, float* __restrict__ out,
                  int n, float invN) {
    int gwarp  = (blockIdx.x * blockDim.x + threadIdx.x) >> 5;
    int lane   = threadIdx.x & 31;
    int nwarps = (gridDim.x * blockDim.x) >> 5;
    const __half2* base = (const __half2*)g_h2h;
    float2 bb = ((const float2*)b)[lane];
    float2 sum = make_float2(0, 0), sq = make_float2(0, 0);

    for (int node = gwarp; node < n; node += nwarps) {
        int e0 = g_rowptr[node], e1 = g_rowptr[node + 1];
        float2 acc = __half22float2(base[(size_t)node * 32 + lane]);
        int e = e0;
        for (; e + 4 <= e1; e += 4) {
            int i0 = g_col[e], i1 = g_col[e + 1], i2 = g_col[e + 2], i3 = g_col[e + 3];
            float2 v0 = __half22float2(base[(size_t)i0 * 32 + lane]);
            float2 v1 = __half22float2(base[(size_t)i1 * 32 + lane]);
            float2 v2 = __half22float2(base[(size_t)i2 * 32 + lane]);
            float2 v3 = __half22float2(base[(size_t)i3 * 32 + lane]);
            acc.x += (v0.x + v1.x) + (v2.x + v3.x);
            acc.y += (v0.y + v1.y) + (v2.y + v3.y);
        }
        for (; e < e1; e++) {
            float2 v = __half22float2(base[(size_t)g_col[e] * 32 + lane]);
            acc.x += v.x; acc.y += v.y;
        }
        float d = g_dinv[node];
        float2 o;
        o.x = fmaf(acc.x, d, bb.x); o.y = fmaf(acc.y, d, bb.y);
        ((float2*)out)[(size_t)node * 32 + lane] = o;
        sum.x += o.x; sum.y += o.y;
        sq.x += o.x * o.x; sq.y += o.y * o.y;
    }
    __shared__ float ssum[OUTC], ssq[OUTC];
    __shared__ float sS[OUTC], sT[OUTC];
    int t = threadIdx.x;
    if (t < OUTC) { ssum[t] = 0.f; ssq[t] = 0.f; }
    __syncthreads();
    int c0 = lane * 2;
    atomicAdd(&ssum[c0 + 0], sum.x); atomicAdd(&ssum[c0 + 1], sum.y);
    atomicAdd(&ssq[c0 + 0], sq.x);  atomicAdd(&ssq[c0 + 1], sq.y);
    __syncthreads();
    if (t < OUTC) {
        atomicAdd(&g_stats2[t], ssum[t]);
        atomicAdd(&g_stats2[OUTC + t], ssq[t]);
    }
    __threadfence();
    __shared__ int isLast;
    __syncthreads();
    if (t == 0) isLast = (atomicAdd(&g_ctr2, 1) == (int)gridDim.x - 1);
    __syncthreads();
    if (isLast) {
        if (t < OUTC) {
            float mean = g_stats2[t] * invN;
            float var  = g_stats2[OUTC + t] * invN - mean * mean;
            float sc = gamma[t] * rsqrtf(var + EPS);
            g_stats2[2 * OUTC + t] = sc;
            g_stats2[3 * OUTC + t] = beta[t] - mean * sc;
        }
        __threadfence();
        __syncthreads();
        if (t == 0) atomicExch(&g_flag2, 1);
    }
    if (t == 0) { while (atomicAdd(&g_flag2, 0) == 0) { } }
    __syncthreads();
    if (t < OUTC) { sS[t] = g_stats2[2 * OUTC + t]; sT[t] = g_stats2[3 * OUTC + t]; }
    __syncthreads();
    int gtid = blockIdx.x * blockDim.x + t;
    int stride = gridDim.x * blockDim.x;
    int total4 = n * (OUTC / 4);
    float4* o4 = (float4*)out;
    for (int i = gtid; i < total4; i += stride) {
        float4 v = o4[i];
        int c = (i & 15) * 4;
        v.x = fmaf(v.x, sS[c + 0], sT[c + 0]);
        v.y = fmaf(v.y, sS[c + 1], sT[c + 1]);
        v.z = fmaf(v.z, sS[c + 2], sT[c + 2]);
        v.w = fmaf(v.w, sS[c + 3], sT[c + 3]);
        o4[i] = v;
    }
}

extern "C" void kernel_launch(void* const* d_in, const int* in_sizes, int n_in,
                              void* d_out, int out_size) {
    const float* x      = (const float*)d_in[0];
    const float* W1     = (const float*)d_in[1];
    const float* b1     = (const float*)d_in[2];
    const float* gamma1 = (const float*)d_in[3];
    const float* beta1  = (const float*)d_in[4];
    const float* W2     = (const float*)d_in[5];
    const float* b2     = (const float*)d_in[6];
    const float* gamma2 = (const float*)d_in[7];
    const float* beta2  = (const float*)d_in[8];
    const int*   ei     = (const int*)d_in[9];
    float*       out    = (float*)d_out;

    int N = in_sizes[0] / INC;     // 100000
    int E = in_sizes[9] / 2;       // 1600000
    const int* src = ei;
    const int* dst = ei + E;
    float invN = 1.0f / (float)N;

    const int SMEM1 = 1024 + 2 * 128 * ASTR * 2 + 2 * 128 * ASTR * 2;  // 140288
    const int SMEM2 = 1024 + 2 * 128 * ASTR * 2 + 2 * 64 * ASTR * 2;   // 105472

    static cudaStream_t s2 = nullptr;
    static cudaEvent_t  evC = nullptr, ev1 = nullptr;
    static int first = 1;
    if (first) {
        cudaFuncSetAttribute(mmagemm_kernel<128, false, true, false>,
                             cudaFuncAttributeMaxDynamicSharedMemorySize, SMEM1);
        cudaFuncSetAttribute(mmagemm_kernel<64, true, false, true>,
                             cudaFuncAttributeMaxDynamicSharedMemorySize, SMEM2);
        cudaStreamCreateWithFlags(&s2, cudaStreamNonBlocking);
        cudaEventCreateWithFlags(&evC, cudaEventDisableTiming);
        cudaEventCreateWithFlags(&ev1, cudaEventDisableTiming);
        // one-time: zero barrier slots so the first A launch is well-defined
        int zeros[4] = {0, 0, 0, 0};
        cudaMemcpyToSymbol(g_gbar, zeros, sizeof(zeros));
        cudaMemcpyToSymbol(g_gflag, zeros, sizeof(zeros));
        cudaDeviceSynchronize();
        first = 0;
    }

    int nb = (N + 1023) / 1024;   // 98
    int gblk = (N + 127) / 128;

    // ---- A: zero + count (fused, one grid barrier) ----
    build_a_kernel<<<nb, 1024>>>(dst, N, E / 4);
    cudaEventRecord(evC, 0);

    // ---- side: GEMM1 (epilogue reads g_cnt) ----
    cudaStreamWaitEvent(s2, evC, 0);
    mmagemm_kernel<128, false, true, false><<<gblk, 256, SMEM1, s2>>>(x, W1, N);
    cudaEventRecord(ev1, s2);

    // ---- B: scan + rowptr/dinv + fill (fused, two grid barriers); overlaps GEMM1 ----
    build_b_kernel<<<nb, 1024>>>(src, dst, N, E / 4);

    // ---- join ----
    cudaStreamWaitEvent(0, ev1, 0);

    // aggregate layer 1 (+bias, +BN1 stats+params) -> fp16 a1
    agg128_kernel<<<1024, 256>>>(b1, gamma1, beta1, N, invN);
    // h2 = (relu(bn1(a1)) @ W2) * dinv -> fp16
    mmagemm_kernel<64, true, false, true><<<gblk, 256, SMEM2>>>(nullptr, W2, N);
    // aggregate layer 2 into d_out (+BN2 stats+params+apply)
    agg64_kernel<<<512, 256>>>(b2, gamma2, beta2, out, N, invN);
}

// round 12
// speedup vs baseline: 1.0809x; 1.0809x over previous
#include <cuda_runtime.h>
#include <cuda_bf16.h>
#include <cuda_fp16.h>
#include <cstdint>

#define NMAX 100000
#define EMAX 1600000
#define INC  128
#define HID  128
#define OUTC 64
#define EPS  1e-5f

// ---------------- scratch (no allocations allowed) ----------------
__device__ int    g_cnt[NMAX];
__device__ int    g_rowptr[NMAX + 1];
__device__ int    g_fill[NMAX];
__device__ int    g_col[EMAX];
__device__ float  g_dinv[NMAX];
__device__ int    g_bsum[128];
__device__ int    g_ctr1, g_ctr2, g_flag2;
__device__ __half g_h1h[(size_t)NMAX * HID];   // (x@W1)*dinv[row], fp16
__device__ __half g_a1h[(size_t)NMAX * HID];   // aggregated layer-1 (pre-BN), fp16
__device__ __half g_h2h[(size_t)NMAX * OUTC];  // (relu(bn1)@W2)*dinv[row], fp16
__device__ float  g_stats1[4 * HID];           // sum | sq | s | t
__device__ float  g_stats2[4 * OUTC];

// ---------------- helpers ----------------
__device__ __forceinline__ uint32_t smem_u32(const void* p) {
    uint32_t a;
    asm("{ .reg .u64 t; cvta.to.shared.u64 t, %1; cvt.u32.u64 %0, t; }" : "=r"(a) : "l"(p));
    return a;
}
__device__ __forceinline__ void ldmatrix_x4(uint32_t* r, uint32_t addr) {
    asm volatile("ldmatrix.sync.aligned.m8n8.x4.shared.b16 {%0,%1,%2,%3}, [%4];"
                 : "=r"(r[0]), "=r"(r[1]), "=r"(r[2]), "=r"(r[3]) : "r"(addr));
}
__device__ __forceinline__ void mma_bf16(float* c, const uint32_t* a, uint32_t b0, uint32_t b1) {
    asm volatile(
        "mma.sync.aligned.m16n8k16.row.col.f32.bf16.bf16.f32 "
        "{%0,%1,%2,%3}, {%4,%5,%6,%7}, {%8,%9}, {%0,%1,%2,%3};"
        : "+f"(c[0]), "+f"(c[1]), "+f"(c[2]), "+f"(c[3])
        : "r"(a[0]), "r"(a[1]), "r"(a[2]), "r"(a[3]), "r"(b0), "r"(b1));
}

// ---------------- init ----------------
__global__ void zero_kernel(int n) {
    int i = blockIdx.x * blockDim.x + threadIdx.x;
    if (i < n)        g_cnt[i] = 0;
    if (i < 4 * HID)  g_stats1[i] = 0.f;
    if (i < 4 * OUTC) g_stats2[i] = 0.f;
    if (i == 0) { g_ctr1 = 0; g_ctr2 = 0; g_flag2 = 0; }
}

// ---------------- degree count ----------------
__global__ void count_kernel(const int* __restrict__ dst, int E) {
    int i = blockIdx.x * blockDim.x + threadIdx.x;
    if (i < E) atomicAdd(&g_cnt[dst[i]], 1);
}

// ---------------- 2-pass parallel scan ----------------
__global__ void scan1_kernel(int n) {
    __shared__ int ws[32];
    int tid = threadIdx.x, lane = tid & 31, w = tid >> 5;
    int i = blockIdx.x * 1024 + tid;
    int v = (i < n) ? g_cnt[i] : 0;
    int x = v;
    #pragma unroll
    for (int off = 1; off < 32; off <<= 1) {
        int y = __shfl_up_sync(0xffffffffu, x, off);
        if (lane >= off) x += y;
    }
    if (lane == 31) ws[w] = x;
    __syncthreads();
    if (w == 0) {
        int y = ws[lane];
        #pragma unroll
        for (int off = 1; off < 32; off <<= 1) {
            int z = __shfl_up_sync(0xffffffffu, y, off);
            if (lane >= off) y += z;
        }
        ws[lane] = y;
    }
    __syncthreads();
    int incl = x + (w ? ws[w - 1] : 0);
    if (i < n) g_fill[i] = incl - v;
    if (tid == 1023) g_bsum[blockIdx.x] = incl;
}
__global__ void scan3_kernel(int n, int nb) {
    __shared__ int excl[128];
    __shared__ int wsum[4];
    int tid = threadIdx.x, lane = tid & 31, w = tid >> 5;
    int xv = 0, vv = 0;
    if (tid < 128) {
        vv = (tid < nb) ? g_bsum[tid] : 0;
        xv = vv;
        #pragma unroll
        for (int off = 1; off < 32; off <<= 1) {
            int y = __shfl_up_sync(0xffffffffu, xv, off);
            if (lane >= off) xv += y;
        }
        if (lane == 31) wsum[w] = xv;
    }
    __syncthreads();
    if (tid < 128) {
        int add = 0;
        #pragma unroll
        for (int j = 0; j < 4; j++) if (j < w) add += wsum[j];
        excl[tid] = xv - vv + add;
    }
    __syncthreads();
    int off = excl[blockIdx.x];
    int i = blockIdx.x * 1024 + tid;
    if (i < n) {
        int c = g_cnt[i];
        int ex = g_fill[i] + off;
        g_fill[i] = ex;
        g_rowptr[i + 1] = ex + c;
        g_dinv[i] = rsqrtf((float)(c + 1));
        if (i == 0) g_rowptr[0] = 0;
    }
}

// ---------------- CSR fill ----------------
__global__ void fill_kernel(const int* __restrict__ src, const int* __restrict__ dst, int E) {
    int i = blockIdx.x * blockDim.x + threadIdx.x;
    if (i < E) {
        int d = dst[i];
        int pos = atomicAdd(&g_fill[d], 1);
        g_col[pos] = src[i];
    }
}

// ---------------- HMMA bf16 GEMM (unchanged from R9) ----------------
#define ASTR 136
template <int TN, bool PRE_BN, bool DINVC, bool DINV>
__global__ __launch_bounds__(256)
void mmagemm_kernel(const float* __restrict__ Aext, const float* __restrict__ W, int M) {
    extern __shared__ char smem[];
    const uint32_t SM_ST = 0;
    const uint32_t A_HI  = 1024;
    const uint32_t A_LO  = A_HI + 128 * ASTR * 2;
    const uint32_t B_HI  = A_LO + 128 * ASTR * 2;
    const uint32_t B_LO  = B_HI + TN * ASTR * 2;

    uint32_t sb = smem_u32(smem);
    int tid = threadIdx.x, wid = tid >> 5, lane = tid & 31;
    int m0 = blockIdx.x * 128;

    if (PRE_BN && tid < 256) {
        float v = (tid < 128) ? g_stats1[2 * HID + tid] : g_stats1[3 * HID + (tid - 128)];
        *(float*)(smem + SM_ST + tid * 4) = v;
    }

    __half* Cout = PRE_BN ? g_h2h : g_h1h;
    const float* s = (const float*)(smem + SM_ST);
    const float* t = s + 128;
    if (PRE_BN) __syncthreads();

    if (PRE_BN) {
        #pragma unroll
        for (int it = 0; it < 8; ++it) {
            int idx = tid + it * 256;
            int row = idx >> 4;
            int c8  = (idx & 15) * 8;
            uint4 u = make_uint4(0, 0, 0, 0);
            if (m0 + row < M) u = *(const uint4*)&g_a1h[(size_t)(m0 + row) * 128 + c8];
            const __half2* hp = (const __half2*)&u;
            uint32_t off = (uint32_t)row * (ASTR * 2) + (uint32_t)c8 * 2;
            #pragma unroll
            for (int j = 0; j < 4; j++) {
                float2 f = __half22float2(hp[j]);
                int k = c8 + 2 * j;
                f.x = fmaxf(fmaf(f.x, s[k + 0], t[k + 0]), 0.f);
                f.y = fmaxf(fmaf(f.y, s[k + 1], t[k + 1]), 0.f);
                __nv_bfloat162 h = __floats2bfloat162_rn(f.x, f.y);
                __nv_bfloat162 l = __floats2bfloat162_rn(f.x - __bfloat162float(h.x),
                                                         f.y - __bfloat162float(h.y));
                *(__nv_bfloat162*)(smem + A_HI + off + 4 * j) = h;
                *(__nv_bfloat162*)(smem + A_LO + off + 4 * j) = l;
            }
        }
    } else {
        #pragma unroll
        for (int it = 0; it < 16; ++it) {
            int idx = tid + it * 256;
            int row = idx >> 5;
            int col = (idx & 31) << 2;
            float4 v = make_float4(0.f, 0.f, 0.f, 0.f);
            if (m0 + row < M) v = *(const float4*)&Aext[(size_t)(m0 + row) * 128 + col];
            __nv_bfloat162 h01 = __floats2bfloat162_rn(v.x, v.y);
            __nv_bfloat162 h23 = __floats2bfloat162_rn(v.z, v.w);
            __nv_bfloat162 l01 = __floats2bfloat162_rn(v.x - __bfloat162float(h01.x),
                                                       v.y - __bfloat162float(h01.y));
            __nv_bfloat162 l23 = __floats2bfloat162_rn(v.z - __bfloat162float(h23.x),
                                                       v.w - __bfloat162float(h23.y));
            uint32_t off = (uint32_t)row * (ASTR * 2) + (uint32_t)col * 2;
            *(__nv_bfloat162*)(smem + A_HI + off)     = h01;
            *(__nv_bfloat162*)(smem + A_HI + off + 4) = h23;
            *(__nv_bfloat162*)(smem + A_LO + off)     = l01;
            *(__nv_bfloat162*)(smem + A_LO + off + 4) = l23;
        }
    }
    for (int idx = tid; idx < 128 * TN; idx += 256) {
        int k = idx / TN, n = idx % TN;
        float w = W[idx];
        __nv_bfloat16 hi = __float2bfloat16_rn(w);
        __nv_bfloat16 lo = __float2bfloat16_rn(w - __bfloat162float(hi));
        uint32_t off = (uint32_t)n * (ASTR * 2) + (uint32_t)k * 2;
        *(__nv_bfloat16*)(smem + B_HI + off) = hi;
        *(__nv_bfloat16*)(smem + B_LO + off) = lo;
    }
    __syncthreads();

    constexpr int WN   = TN / 2;
    constexpr int NSUB = WN / 8;
    int m_base = (wid & 3) * 32;
    int n_base = (wid >> 2) * WN;
    int g = lane >> 2, tt = lane & 3;

    float acc[2][NSUB][4];
    #pragma unroll
    for (int mi = 0; mi < 2; mi++)
        #pragma unroll
        for (int ni = 0; ni < NSUB; ni++)
            #pragma unroll
            for (int j = 0; j < 4; j++) acc[mi][ni][j] = 0.f;

    uint32_t a_row = (uint32_t)(m_base + (lane & 15));
    uint32_t a_cb  = (uint32_t)((lane >> 4) * 8);

    #pragma unroll
    for (int term = 0; term < 3; ++term) {
        uint32_t Abase = sb + ((term == 1) ? A_LO : A_HI);
        uint32_t Bbase = ((term == 2) ? B_LO : B_HI);
        #pragma unroll
        for (int ks = 0; ks < 8; ++ks) {
            int k0 = ks * 16;
            uint32_t af[2][4];
            #pragma unroll
            for (int mi = 0; mi < 2; mi++) {
                uint32_t addr = Abase + (a_row + mi * 16) * (ASTR * 2) + (a_cb + k0) * 2;
                ldmatrix_x4(af[mi], addr);
            }
            const char* brow = smem + Bbase + (uint32_t)(n_base + g) * (ASTR * 2) + (uint32_t)(k0 + 2 * tt) * 2;
            #pragma unroll
            for (int ni = 0; ni < NSUB; ni++) {
                uint32_t b0 = *(const uint32_t*)(brow + ni * 8 * (ASTR * 2));
                uint32_t b1 = *(const uint32_t*)(brow + ni * 8 * (ASTR * 2) + 16);
                mma_bf16(acc[0][ni], af[0], b0, b1);
                mma_bf16(acc[1][ni], af[1], b0, b1);
            }
        }
    }

    #pragma unroll
    for (int mi = 0; mi < 2; mi++) {
        int r0 = m0 + m_base + mi * 16 + g;
        int r1 = r0 + 8;
        float d0 = 1.f, d1 = 1.f;
        if (DINVC) {
            d0 = (r0 < M) ? rsqrtf((float)(g_cnt[r0] + 1)) : 0.f;
            d1 = (r1 < M) ? rsqrtf((float)(g_cnt[r1] + 1)) : 0.f;
        }
        if (DINV) {
            d0 = (r0 < M) ? g_dinv[r0] : 0.f;
            d1 = (r1 < M) ? g_dinv[r1] : 0.f;
        }
        #pragma unroll
        for (int ni = 0; ni < NSUB; ni++) {
            int col = n_base + ni * 8 + 2 * tt;
            if (r0 < M)
                *(__half2*)&Cout[(size_t)r0 * TN + col] =
                    __floats2half2_rn(acc[mi][ni][0] * d0, acc[mi][ni][1] * d0);
            if (r1 < M)
                *(__half2*)&Cout[(size_t)r1 * TN + col] =
                    __floats2half2_rn(acc[mi][ni][2] * d1, acc[mi][ni][3] * d1);
        }
    }
}

// ---------------- aggregation helpers ----------------
__device__ __forceinline__ float4 h4_to_f4(uint2 u) {
    float2 a = __half22float2(*(__half2*)&u.x);
    float2 b = __half22float2(*(__half2*)&u.y);
    return make_float4(a.x, a.y, b.x, b.y);
}
__device__ __forceinline__ void acc4(float4& a, uint2 u) {
    float4 v = h4_to_f4(u);
    a.x += v.x; a.y += v.y; a.z += v.z; a.w += v.w;
}

// ---------------- aggregation, 128 cols; MLP-8 gather; fused BN1 params ----------------
__global__ __launch_bounds__(256)
void agg128_kernel(const float* __restrict__ b, const float* __restrict__ gamma,
                   const float* __restrict__ beta, int n, float invN) {
    int gwarp  = (blockIdx.x * blockDim.x + threadIdx.x) >> 5;
    int lane   = threadIdx.x & 31;
    int nwarps = (gridDim.x * blockDim.x) >> 5;
    const uint2* base = (const uint2*)g_h1h;
    float4 bb = ((const float4*)b)[lane];
    float4 sum = make_float4(0, 0, 0, 0), sq = make_float4(0, 0, 0, 0);

    for (int node = gwarp; node < n; node += nwarps) {
        int e0 = g_rowptr[node], e1 = g_rowptr[node + 1];
        float4 acc = h4_to_f4(base[(size_t)node * 32 + lane]);  // self-loop
        int e = e0;
        // 8-wide: batch index loads, then 8 independent gathers in flight
        for (; e + 8 <= e1; e += 8) {
            int i0 = g_col[e],     i1 = g_col[e + 1], i2 = g_col[e + 2], i3 = g_col[e + 3];
            int i4 = g_col[e + 4], i5 = g_col[e + 5], i6 = g_col[e + 6], i7 = g_col[e + 7];
            uint2 v0 = base[(size_t)i0 * 32 + lane];
            uint2 v1 = base[(size_t)i1 * 32 + lane];
            uint2 v2 = base[(size_t)i2 * 32 + lane];
            uint2 v3 = base[(size_t)i3 * 32 + lane];
            uint2 v4 = base[(size_t)i4 * 32 + lane];
            uint2 v5 = base[(size_t)i5 * 32 + lane];
            uint2 v6 = base[(size_t)i6 * 32 + lane];
            uint2 v7 = base[(size_t)i7 * 32 + lane];
            acc4(acc, v0); acc4(acc, v1); acc4(acc, v2); acc4(acc, v3);
            acc4(acc, v4); acc4(acc, v5); acc4(acc, v6); acc4(acc, v7);
        }
        for (; e + 4 <= e1; e += 4) {
            int i0 = g_col[e], i1 = g_col[e + 1], i2 = g_col[e + 2], i3 = g_col[e + 3];
            uint2 v0 = base[(size_t)i0 * 32 + lane];
            uint2 v1 = base[(size_t)i1 * 32 + lane];
            uint2 v2 = base[(size_t)i2 * 32 + lane];
            uint2 v3 = base[(size_t)i3 * 32 + lane];
            acc4(acc, v0); acc4(acc, v1); acc4(acc, v2); acc4(acc, v3);
        }
        for (; e < e1; e++) acc4(acc, base[(size_t)g_col[e] * 32 + lane]);
        float d = g_dinv[node];
        float4 o;
        o.x = fmaf(acc.x, d, bb.x); o.y = fmaf(acc.y, d, bb.y);
        o.z = fmaf(acc.z, d, bb.z); o.w = fmaf(acc.w, d, bb.w);
        uint2 st;
        *(__half2*)&st.x = __floats2half2_rn(o.x, o.y);
        *(__half2*)&st.y = __floats2half2_rn(o.z, o.w);
        ((uint2*)g_a1h)[(size_t)node * 32 + lane] = st;
        sum.x += o.x; sum.y += o.y; sum.z += o.z; sum.w += o.w;
        sq.x += o.x * o.x; sq.y += o.y * o.y; sq.z += o.z * o.z; sq.w += o.w * o.w;
    }
    __shared__ float ssum[HID], ssq[HID];
    int t = threadIdx.x;
    if (t < HID) { ssum[t] = 0.f; ssq[t] = 0.f; }
    __syncthreads();
    int c0 = lane * 4;
    atomicAdd(&ssum[c0 + 0], sum.x); atomicAdd(&ssum[c0 + 1], sum.y);
    atomicAdd(&ssum[c0 + 2], sum.z); atomicAdd(&ssum[c0 + 3], sum.w);
    atomicAdd(&ssq[c0 + 0], sq.x);  atomicAdd(&ssq[c0 + 1], sq.y);
    atomicAdd(&ssq[c0 + 2], sq.z);  atomicAdd(&ssq[c0 + 3], sq.w);
    __syncthreads();
    if (t < HID) {
        atomicAdd(&g_stats1[t], ssum[t]);
        atomicAdd(&g_stats1[HID + t], ssq[t]);
    }
    __threadfence();
    __shared__ int isLast;
    __syncthreads();
    if (t == 0) isLast = (atomicAdd(&g_ctr1, 1) == (int)gridDim.x - 1);
    __syncthreads();
    if (isLast && t < HID) {
        float mean = g_stats1[t] * invN;
        float var  = g_stats1[HID + t] * invN - mean * mean;
        float sc = gamma[t] * rsqrtf(var + EPS);
        g_stats1[2 * HID + t] = sc;
        g_stats1[3 * HID + t] = beta[t] - mean * sc;
    }
}

// ---------------- aggregation, 64 cols; MLP-8 gather; fused grid-barrier BN2 apply ----------------
__global__ __launch_bounds__(256, 4)
void agg64_kernel(const float* __restrict__ b, const float* __restrict__ gamma,
                  const float* __restrict__ beta, float* __restrict__ out,
                  int n, float invN) {
    int gwarp  = (blockIdx.x * blockDim.x + threadIdx.x) >> 5;
    int lane   = threadIdx.x & 31;
    int nwarps = (gridDim.x * blockDim.x) >> 5;
    const __half2* base = (const __half2*)g_h2h;
    float2 bb = ((const float2*)b)[lane];
    float2 sum = make_float2(0, 0), sq = make_float2(0, 0);

    for (int node = gwarp; node < n; node += nwarps) {
        int e0 = g_rowptr[node], e1 = g_rowptr[node + 1];
        float2 acc = __half22float2(base[(size_t)node * 32 + lane]);
        int e = e0;
        for (; e + 8 <= e1; e += 8) {
            int i0 = g_col[e],     i1 = g_col[e + 1], i2 = g_col[e + 2], i3 = g_col[e + 3];
            int i4 = g_col[e + 4], i5 = g_col[e + 5], i6 = g_col[e + 6], i7 = g_col[e + 7];
            __half2 h0 = base[(size_t)i0 * 32 + lane];
            __half2 h1 = base[(size_t)i1 * 32 + lane];
            __half2 h2 = base[(size_t)i2 * 32 + lane];
            __half2 h3 = base[(size_t)i3 * 32 + lane];
            __half2 h4 = base[(size_t)i4 * 32 + lane];
            __half2 h5 = base[(size_t)i5 * 32 + lane];
            __half2 h6 = base[(size_t)i6 * 32 + lane];
            __half2 h7 = base[(size_t)i7 * 32 + lane];
            float2 f;
            f = __half22float2(h0); acc.x += f.x; acc.y += f.y;
            f = __half22float2(h1); acc.x += f.x; acc.y += f.y;
            f = __half22float2(h2); acc.x += f.x; acc.y += f.y;
            f = __half22float2(h3); acc.x += f.x; acc.y += f.y;
            f = __half22float2(h4); acc.x += f.x; acc.y += f.y;
            f = __half22float2(h5); acc.x += f.x; acc.y += f.y;
            f = __half22float2(h6); acc.x += f.x; acc.y += f.y;
            f = __half22float2(h7); acc.x += f.x; acc.y += f.y;
        }
        for (; e + 4 <= e1; e += 4) {
            int i0 = g_col[e], i1 = g_col[e + 1], i2 = g_col[e + 2], i3 = g_col[e + 3];
            float2 v0 = __half22float2(base[(size_t)i0 * 32 + lane]);
            float2 v1 = __half22float2(base[(size_t)i1 * 32 + lane]);
            float2 v2 = __half22float2(base[(size_t)i2 * 32 + lane]);
            float2 v3 = __half22float2(base[(size_t)i3 * 32 + lane]);
            acc.x += (v0.x + v1.x) + (v2.x + v3.x);
            acc.y += (v0.y + v1.y) + (v2.y + v3.y);
        }
        for (; e < e1; e++) {
            float2 v = __half22float2(base[(size_t)g_col[e] * 32 + lane]);
            acc.x += v.x; acc.y += v.y;
        }
        float d = g_dinv[node];
        float2 o;
        o.x = fmaf(acc.x, d, bb.x); o.y = fmaf(acc.y, d, bb.y);
        ((float2*)out)[(size_t)node * 32 + lane] = o;
        sum.x += o.x; sum.y += o.y;
        sq.x += o.x * o.x; sq.y += o.y * o.y;
    }
    __shared__ float ssum[OUTC], ssq[OUTC];
    __shared__ float sS[OUTC], sT[OUTC];
    int t = threadIdx.x;
    if (t < OUTC) { ssum[t] = 0.f; ssq[t] = 0.f; }
    __syncthreads();
    int c0 = lane * 2;
    atomicAdd(&ssum[c0 + 0], sum.x); atomicAdd(&ssum[c0 + 1], sum.y);
    atomicAdd(&ssq[c0 + 0], sq.x);  atomicAdd(&ssq[c0 + 1], sq.y);
    __syncthreads();
    if (t < OUTC) {
        atomicAdd(&g_stats2[t], ssum[t]);
        atomicAdd(&g_stats2[OUTC + t], ssq[t]);
    }
    __threadfence();
    __shared__ int isLast;
    __syncthreads();
    if (t == 0) isLast = (atomicAdd(&g_ctr2, 1) == (int)gridDim.x - 1);
    __syncthreads();
    if (isLast) {
        if (t < OUTC) {
            float mean = g_stats2[t] * invN;
            float var  = g_stats2[OUTC + t] * invN - mean * mean;
            float sc = gamma[t] * rsqrtf(var + EPS);
            g_stats2[2 * OUTC + t] = sc;
            g_stats2[3 * OUTC + t] = beta[t] - mean * sc;
        }
        __threadfence();
        __syncthreads();
        if (t == 0) atomicExch(&g_flag2, 1);
    }
    if (t == 0) { while (atomicAdd(&g_flag2, 0) == 0) { } }
    __syncthreads();
    if (t < OUTC) { sS[t] = g_stats2[2 * OUTC + t]; sT[t] = g_stats2[3 * OUTC + t]; }
    __syncthreads();
    int gtid = blockIdx.x * blockDim.x + t;
    int stride = gridDim.x * blockDim.x;
    int total4 = n * (OUTC / 4);
    float4* o4 = (float4*)out;
    for (int i = gtid; i < total4; i += stride) {
        float4 v = o4[i];
        int c = (i & 15) * 4;
        v.x = fmaf(v.x, sS[c + 0], sT[c + 0]);
        v.y = fmaf(v.y, sS[c + 1], sT[c + 1]);
        v.z = fmaf(v.z, sS[c + 2], sT[c + 2]);
        v.w = fmaf(v.w, sS[c + 3], sT[c + 3]);
        o4[i] = v;
    }
}

extern "C" void kernel_launch(void* const* d_in, const int* in_sizes, int n_in,
                              void* d_out, int out_size) {
    const float* x      = (const float*)d_in[0];
    const float* W1     = (const float*)d_in[1];
    const float* b1     = (const float*)d_in[2];
    const float* gamma1 = (const float*)d_in[3];
    const float* beta1  = (const float*)d_in[4];
    const float* W2     = (const float*)d_in[5];
    const float* b2     = (const float*)d_in[6];
    const float* gamma2 = (const float*)d_in[7];
    const float* beta2  = (const float*)d_in[8];
    const int*   ei     = (const int*)d_in[9];
    float*       out    = (float*)d_out;

    int N = in_sizes[0] / INC;     // 100000
    int E = in_sizes[9] / 2;       // 1600000
    const int* src = ei;
    const int* dst = ei + E;
    float invN = 1.0f / (float)N;

    const int SMEM1 = 1024 + 2 * 128 * ASTR * 2 + 2 * 128 * ASTR * 2;  // 140288
    const int SMEM2 = 1024 + 2 * 128 * ASTR * 2 + 2 * 64 * ASTR * 2;   // 105472

    static cudaStream_t s2 = nullptr;
    static cudaEvent_t  evC = nullptr, ev1 = nullptr;
    if (!s2) {
        cudaFuncSetAttribute(mmagemm_kernel<128, false, true, false>,
                             cudaFuncAttributeMaxDynamicSharedMemorySize, SMEM1);
        cudaFuncSetAttribute(mmagemm_kernel<64, true, false, true>,
                             cudaFuncAttributeMaxDynamicSharedMemorySize, SMEM2);
        cudaStreamCreateWithFlags(&s2, cudaStreamNonBlocking);
        cudaEventCreateWithFlags(&evC, cudaEventDisableTiming);
        cudaEventCreateWithFlags(&ev1, cudaEventDisableTiming);
    }

    int nb = (N + 1023) / 1024;
    int gblk = (N + 127) / 128;

    // ---- main: degree counts ----
    zero_kernel<<<(N + 255) / 256, 256>>>(N);
    count_kernel<<<(E + 255) / 256, 256>>>(dst, E);
    cudaEventRecord(evC, 0);

    // ---- side: GEMM1 with dinv folded from counts ----
    cudaStreamWaitEvent(s2, evC, 0);
    mmagemm_kernel<128, false, true, false><<<gblk, 256, SMEM1, s2>>>(x, W1, N);
    cudaEventRecord(ev1, s2);

    // ---- main: scan + fill (overlaps GEMM1) ----
    scan1_kernel<<<nb, 1024>>>(N);
    scan3_kernel<<<nb, 1024>>>(N, nb);
    fill_kernel<<<(E + 255) / 256, 256>>>(src, dst, E);

    // ---- join ----
    cudaStreamWaitEvent(0, ev1, 0);

    // aggregate layer 1 (+bias, +BN1 stats+params) -> fp16 a1
    agg128_kernel<<<1024, 256>>>(b1, gamma1, beta1, N, invN);
    // h2 = (relu(bn1(a1)) @ W2) * dinv -> fp16
    mmagemm_kernel<64, true, false, true><<<gblk, 256, SMEM2>>>(nullptr, W2, N);
    // aggregate layer 2 into d_out (+BN2 stats+params+apply)
    agg64_kernel<<<512, 256>>>(b2, gamma2, beta2, out, N, invN);
}

// round 13
// speedup vs baseline: 1.1625x; 1.0755x over previous
#include <cuda_runtime.h>
#include <cuda_bf16.h>
#include <cuda_fp16.h>
#include <cstdint>

#define NMAX 100000
#define EMAX 1600000
#define INC  128
#define HID  128
#define OUTC 64
#define EPS  1e-5f

// ---------------- scratch (no allocations allowed) ----------------
__device__ int    g_cnt[NMAX];
__device__ int    g_rowptr[NMAX + 1];
__device__ int    g_fill[NMAX];
__device__ int    g_col[EMAX];
__device__ float  g_dinv[NMAX];
__device__ int    g_bsum[128];
__device__ int    g_ctr1, g_ctr2, g_flag2;
__device__ __half g_h1h[(size_t)NMAX * HID];   // (x@W1)*dinv[row], fp16
__device__ __half g_a1h[(size_t)NMAX * HID];   // aggregated layer-1 (pre-BN), fp16
__device__ __half g_h2h[(size_t)NMAX * OUTC];  // (relu(bn1)@W2)*dinv[row], fp16
__device__ float  g_stats1[4 * HID];           // sum | sq | s | t
__device__ float  g_stats2[4 * OUTC];

// ---------------- helpers ----------------
__device__ __forceinline__ uint32_t smem_u32(const void* p) {
    uint32_t a;
    asm("{ .reg .u64 t; cvta.to.shared.u64 t, %1; cvt.u32.u64 %0, t; }" : "=r"(a) : "l"(p));
    return a;
}
__device__ __forceinline__ void ldmatrix_x4(uint32_t* r, uint32_t addr) {
    asm volatile("ldmatrix.sync.aligned.m8n8.x4.shared.b16 {%0,%1,%2,%3}, [%4];"
                 : "=r"(r[0]), "=r"(r[1]), "=r"(r[2]), "=r"(r[3]) : "r"(addr));
}
__device__ __forceinline__ void mma_bf16(float* c, const uint32_t* a, uint32_t b0, uint32_t b1) {
    asm volatile(
        "mma.sync.aligned.m16n8k16.row.col.f32.bf16.bf16.f32 "
        "{%0,%1,%2,%3}, {%4,%5,%6,%7}, {%8,%9}, {%0,%1,%2,%3};"
        : "+f"(c[0]), "+f"(c[1]), "+f"(c[2]), "+f"(c[3])
        : "r"(a[0]), "r"(a[1]), "r"(a[2]), "r"(a[3]), "r"(b0), "r"(b1));
}

// ---------------- init ----------------
__global__ void zero_kernel(int n) {
    int i = blockIdx.x * blockDim.x + threadIdx.x;
    if (i < n)        g_cnt[i] = 0;
    if (i < 4 * HID)  g_stats1[i] = 0.f;
    if (i < 4 * OUTC) g_stats2[i] = 0.f;
    if (i == 0) { g_ctr1 = 0; g_ctr2 = 0; g_flag2 = 0; }
}

// ---------------- degree count ----------------
__global__ void count_kernel(const int* __restrict__ dst, int E) {
    int i = blockIdx.x * blockDim.x + threadIdx.x;
    if (i < E) atomicAdd(&g_cnt[dst[i]], 1);
}

// ---------------- 2-pass parallel scan ----------------
__global__ void scan1_kernel(int n) {
    __shared__ int ws[32];
    int tid = threadIdx.x, lane = tid & 31, w = tid >> 5;
    int i = blockIdx.x * 1024 + tid;
    int v = (i < n) ? g_cnt[i] : 0;
    int x = v;
    #pragma unroll
    for (int off = 1; off < 32; off <<= 1) {
        int y = __shfl_up_sync(0xffffffffu, x, off);
        if (lane >= off) x += y;
    }
    if (lane == 31) ws[w] = x;
    __syncthreads();
    if (w == 0) {
        int y = ws[lane];
        #pragma unroll
        for (int off = 1; off < 32; off <<= 1) {
            int z = __shfl_up_sync(0xffffffffu, y, off);
            if (lane >= off) y += z;
        }
        ws[lane] = y;
    }
    __syncthreads();
    int incl = x + (w ? ws[w - 1] : 0);
    if (i < n) g_fill[i] = incl - v;
    if (tid == 1023) g_bsum[blockIdx.x] = incl;
}
__global__ void scan3_kernel(int n, int nb) {
    __shared__ int excl[128];
    __shared__ int wsum[4];
    int tid = threadIdx.x, lane = tid & 31, w = tid >> 5;
    int xv = 0, vv = 0;
    if (tid < 128) {
        vv = (tid < nb) ? g_bsum[tid] : 0;
        xv = vv;
        #pragma unroll
        for (int off = 1; off < 32; off <<= 1) {
            int y = __shfl_up_sync(0xffffffffu, xv, off);
            if (lane >= off) xv += y;
        }
        if (lane == 31) wsum[w] = xv;
    }
    __syncthreads();
    if (tid < 128) {
        int add = 0;
        #pragma unroll
        for (int j = 0; j < 4; j++) if (j < w) add += wsum[j];
        excl[tid] = xv - vv + add;
    }
    __syncthreads();
    int off = excl[blockIdx.x];
    int i = blockIdx.x * 1024 + tid;
    if (i < n) {
        int c = g_cnt[i];
        int ex = g_fill[i] + off;
        g_fill[i] = ex;
        g_rowptr[i + 1] = ex + c;
        g_dinv[i] = rsqrtf((float)(c + 1));
        if (i == 0) g_rowptr[0] = 0;
    }
}

// ---------------- CSR fill ----------------
__global__ void fill_kernel(const int* __restrict__ src, const int* __restrict__ dst, int E) {
    int i = blockIdx.x * blockDim.x + threadIdx.x;
    if (i < E) {
        int d = dst[i];
        int pos = atomicAdd(&g_fill[d], 1);
        g_col[pos] = src[i];
    }
}

// ---------------- HMMA bf16 GEMM ----------------
#define ASTR 136
template <int TN, bool PRE_BN, bool DINVC, bool DINV>
__global__ __launch_bounds__(256)
void mmagemm_kernel(const float* __restrict__ Aext, const float* __restrict__ W, int M) {
    extern __shared__ char smem[];
    const uint32_t SM_ST = 0;
    const uint32_t A_HI  = 1024;
    const uint32_t A_LO  = A_HI + 128 * ASTR * 2;
    const uint32_t B_HI  = A_LO + 128 * ASTR * 2;
    const uint32_t B_LO  = B_HI + TN * ASTR * 2;

    uint32_t sb = smem_u32(smem);
    int tid = threadIdx.x, wid = tid >> 5, lane = tid & 31;
    int m0 = blockIdx.x * 128;

    if (PRE_BN && tid < 256) {
        float v = (tid < 128) ? g_stats1[2 * HID + tid] : g_stats1[3 * HID + (tid - 128)];
        *(float*)(smem + SM_ST + tid * 4) = v;
    }

    __half* Cout = PRE_BN ? g_h2h : g_h1h;
    const float* s = (const float*)(smem + SM_ST);
    const float* t = s + 128;
    if (PRE_BN) __syncthreads();

    if (PRE_BN) {
        #pragma unroll
        for (int it = 0; it < 8; ++it) {
            int idx = tid + it * 256;
            int row = idx >> 4;
            int c8  = (idx & 15) * 8;
            uint4 u = make_uint4(0, 0, 0, 0);
            if (m0 + row < M) u = *(const uint4*)&g_a1h[(size_t)(m0 + row) * 128 + c8];
            const __half2* hp = (const __half2*)&u;
            uint32_t off = (uint32_t)row * (ASTR * 2) + (uint32_t)c8 * 2;
            #pragma unroll
            for (int j = 0; j < 4; j++) {
                float2 f = __half22float2(hp[j]);
                int k = c8 + 2 * j;
                f.x = fmaxf(fmaf(f.x, s[k + 0], t[k + 0]), 0.f);
                f.y = fmaxf(fmaf(f.y, s[k + 1], t[k + 1]), 0.f);
                __nv_bfloat162 h = __floats2bfloat162_rn(f.x, f.y);
                __nv_bfloat162 l = __floats2bfloat162_rn(f.x - __bfloat162float(h.x),
                                                         f.y - __bfloat162float(h.y));
                *(__nv_bfloat162*)(smem + A_HI + off + 4 * j) = h;
                *(__nv_bfloat162*)(smem + A_LO + off + 4 * j) = l;
            }
        }
    } else {
        #pragma unroll
        for (int it = 0; it < 16; ++it) {
            int idx = tid + it * 256;
            int row = idx >> 5;
            int col = (idx & 31) << 2;
            float4 v = make_float4(0.f, 0.f, 0.f, 0.f);
            if (m0 + row < M) v = *(const float4*)&Aext[(size_t)(m0 + row) * 128 + col];
            __nv_bfloat162 h01 = __floats2bfloat162_rn(v.x, v.y);
            __nv_bfloat162 h23 = __floats2bfloat162_rn(v.z, v.w);
            __nv_bfloat162 l01 = __floats2bfloat162_rn(v.x - __bfloat162float(h01.x),
                                                       v.y - __bfloat162float(h01.y));
            __nv_bfloat162 l23 = __floats2bfloat162_rn(v.z - __bfloat162float(h23.x),
                                                       v.w - __bfloat162float(h23.y));
            uint32_t off = (uint32_t)row * (ASTR * 2) + (uint32_t)col * 2;
            *(__nv_bfloat162*)(smem + A_HI + off)     = h01;
            *(__nv_bfloat162*)(smem + A_HI + off + 4) = h23;
            *(__nv_bfloat162*)(smem + A_LO + off)     = l01;
            *(__nv_bfloat162*)(smem + A_LO + off + 4) = l23;
        }
    }
    for (int idx = tid; idx < 128 * TN; idx += 256) {
        int k = idx / TN, n = idx % TN;
        float w = W[idx];
        __nv_bfloat16 hi = __float2bfloat16_rn(w);
        __nv_bfloat16 lo = __float2bfloat16_rn(w - __bfloat162float(hi));
        uint32_t off = (uint32_t)n * (ASTR * 2) + (uint32_t)k * 2;
        *(__nv_bfloat16*)(smem + B_HI + off) = hi;
        *(__nv_bfloat16*)(smem + B_LO + off) = lo;
    }
    __syncthreads();

    constexpr int WN   = TN / 2;
    constexpr int NSUB = WN / 8;
    int m_base = (wid & 3) * 32;
    int n_base = (wid >> 2) * WN;
    int g = lane >> 2, tt = lane & 3;

    float acc[2][NSUB][4];
    #pragma unroll
    for (int mi = 0; mi < 2; mi++)
        #pragma unroll
        for (int ni = 0; ni < NSUB; ni++)
            #pragma unroll
            for (int j = 0; j < 4; j++) acc[mi][ni][j] = 0.f;

    uint32_t a_row = (uint32_t)(m_base + (lane & 15));
    uint32_t a_cb  = (uint32_t)((lane >> 4) * 8);

    #pragma unroll
    for (int term = 0; term < 3; ++term) {
        uint32_t Abase = sb + ((term == 1) ? A_LO : A_HI);
        uint32_t Bbase = ((term == 2) ? B_LO : B_HI);
        #pragma unroll
        for (int ks = 0; ks < 8; ++ks) {
            int k0 = ks * 16;
            uint32_t af[2][4];
            #pragma unroll
            for (int mi = 0; mi < 2; mi++) {
                uint32_t addr = Abase + (a_row + mi * 16) * (ASTR * 2) + (a_cb + k0) * 2;
                ldmatrix_x4(af[mi], addr);
            }
            const char* brow = smem + Bbase + (uint32_t)(n_base + g) * (ASTR * 2) + (uint32_t)(k0 + 2 * tt) * 2;
            #pragma unroll
            for (int ni = 0; ni < NSUB; ni++) {
                uint32_t b0 = *(const uint32_t*)(brow + ni * 8 * (ASTR * 2));
                uint32_t b1 = *(const uint32_t*)(brow + ni * 8 * (ASTR * 2) + 16);
                mma_bf16(acc[0][ni], af[0], b0, b1);
                mma_bf16(acc[1][ni], af[1], b0, b1);
            }
        }
    }

    #pragma unroll
    for (int mi = 0; mi < 2; mi++) {
        int r0 = m0 + m_base + mi * 16 + g;
        int r1 = r0 + 8;
        float d0 = 1.f, d1 = 1.f;
        if (DINVC) {
            d0 = (r0 < M) ? rsqrtf((float)(g_cnt[r0] + 1)) : 0.f;
            d1 = (r1 < M) ? rsqrtf((float)(g_cnt[r1] + 1)) : 0.f;
        }
        if (DINV) {
            d0 = (r0 < M) ? g_dinv[r0] : 0.f;
            d1 = (r1 < M) ? g_dinv[r1] : 0.f;
        }
        #pragma unroll
        for (int ni = 0; ni < NSUB; ni++) {
            int col = n_base + ni * 8 + 2 * tt;
            if (r0 < M)
                *(__half2*)&Cout[(size_t)r0 * TN + col] =
                    __floats2half2_rn(acc[mi][ni][0] * d0, acc[mi][ni][1] * d0);
            if (r1 < M)
                *(__half2*)&Cout[(size_t)r1 * TN + col] =
                    __floats2half2_rn(acc[mi][ni][2] * d1, acc[mi][ni][3] * d1);
        }
    }
}

// ---------------- aggregation helpers ----------------
__device__ __forceinline__ float4 h4_to_f4(uint2 u) {
    float2 a = __half22float2(*(__half2*)&u.x);
    float2 b = __half22float2(*(__half2*)&u.y);
    return make_float4(a.x, a.y, b.x, b.y);
}
__device__ __forceinline__ void acc4(float4& a, uint2 u) {
    float4 v = h4_to_f4(u);
    a.x += v.x; a.y += v.y; a.z += v.z; a.w += v.w;
}

// ---------------- aggregation, 128 cols; single-wave grid; fused BN1 params ----------------
__global__ __launch_bounds__(256, 6)
void agg128_kernel(const float* __restrict__ b, const float* __restrict__ gamma,
                   const float* __restrict__ beta, int n, float invN) {
    int gwarp  = (blockIdx.x * blockDim.x + threadIdx.x) >> 5;
    int lane   = threadIdx.x & 31;
    int nwarps = (gridDim.x * blockDim.x) >> 5;
    const uint2* base = (const uint2*)g_h1h;
    float4 bb = ((const float4*)b)[lane];
    float4 sum = make_float4(0, 0, 0, 0), sq = make_float4(0, 0, 0, 0);

    for (int node = gwarp; node < n; node += nwarps) {
        int e0 = g_rowptr[node], e1 = g_rowptr[node + 1];
        float4 acc = h4_to_f4(base[(size_t)node * 32 + lane]);  // self-loop
        int e = e0;
        for (; e + 8 <= e1; e += 8) {
            int i0 = g_col[e],     i1 = g_col[e + 1], i2 = g_col[e + 2], i3 = g_col[e + 3];
            int i4 = g_col[e + 4], i5 = g_col[e + 5], i6 = g_col[e + 6], i7 = g_col[e + 7];
            uint2 v0 = base[(size_t)i0 * 32 + lane];
            uint2 v1 = base[(size_t)i1 * 32 + lane];
            uint2 v2 = base[(size_t)i2 * 32 + lane];
            uint2 v3 = base[(size_t)i3 * 32 + lane];
            uint2 v4 = base[(size_t)i4 * 32 + lane];
            uint2 v5 = base[(size_t)i5 * 32 + lane];
            uint2 v6 = base[(size_t)i6 * 32 + lane];
            uint2 v7 = base[(size_t)i7 * 32 + lane];
            acc4(acc, v0); acc4(acc, v1); acc4(acc, v2); acc4(acc, v3);
            acc4(acc, v4); acc4(acc, v5); acc4(acc, v6); acc4(acc, v7);
        }
        for (; e + 4 <= e1; e += 4) {
            int i0 = g_col[e], i1 = g_col[e + 1], i2 = g_col[e + 2], i3 = g_col[e + 3];
            uint2 v0 = base[(size_t)i0 * 32 + lane];
            uint2 v1 = base[(size_t)i1 * 32 + lane];
            uint2 v2 = base[(size_t)i2 * 32 + lane];
            uint2 v3 = base[(size_t)i3 * 32 + lane];
            acc4(acc, v0); acc4(acc, v1); acc4(acc, v2); acc4(acc, v3);
        }
        for (; e < e1; e++) acc4(acc, base[(size_t)g_col[e] * 32 + lane]);
        float d = g_dinv[node];
        float4 o;
        o.x = fmaf(acc.x, d, bb.x); o.y = fmaf(acc.y, d, bb.y);
        o.z = fmaf(acc.z, d, bb.z); o.w = fmaf(acc.w, d, bb.w);
        uint2 st;
        *(__half2*)&st.x = __floats2half2_rn(o.x, o.y);
        *(__half2*)&st.y = __floats2half2_rn(o.z, o.w);
        ((uint2*)g_a1h)[(size_t)node * 32 + lane] = st;
        sum.x += o.x; sum.y += o.y; sum.z += o.z; sum.w += o.w;
        sq.x += o.x * o.x; sq.y += o.y * o.y; sq.z += o.z * o.z; sq.w += o.w * o.w;
    }
    __shared__ float ssum[HID], ssq[HID];
    int t = threadIdx.x;
    if (t < HID) { ssum[t] = 0.f; ssq[t] = 0.f; }
    __syncthreads();
    int c0 = lane * 4;
    atomicAdd(&ssum[c0 + 0], sum.x); atomicAdd(&ssum[c0 + 1], sum.y);
    atomicAdd(&ssum[c0 + 2], sum.z); atomicAdd(&ssum[c0 + 3], sum.w);
    atomicAdd(&ssq[c0 + 0], sq.x);  atomicAdd(&ssq[c0 + 1], sq.y);
    atomicAdd(&ssq[c0 + 2], sq.z);  atomicAdd(&ssq[c0 + 3], sq.w);
    __syncthreads();
    if (t < HID) {
        atomicAdd(&g_stats1[t], ssum[t]);
        atomicAdd(&g_stats1[HID + t], ssq[t]);
    }
    __threadfence();
    __shared__ int isLast;
    __syncthreads();
    if (t == 0) isLast = (atomicAdd(&g_ctr1, 1) == (int)gridDim.x - 1);
    __syncthreads();
    if (isLast && t < HID) {
        float mean = g_stats1[t] * invN;
        float var  = g_stats1[HID + t] * invN - mean * mean;
        float sc = gamma[t] * rsqrtf(var + EPS);
        g_stats1[2 * HID + t] = sc;
        g_stats1[3 * HID + t] = beta[t] - mean * sc;
    }
}

// ---------------- aggregation, 64 cols; fused grid-barrier BN2 apply ----------------
__global__ __launch_bounds__(256, 4)
void agg64_kernel(const float* __restrict__ b, const float* __restrict__ gamma,
                  const float* __restrict__ beta, float* __restrict__ out,
                  int n, float invN) {
    int gwarp  = (blockIdx.x * blockDim.x + threadIdx.x) >> 5;
    int lane   = threadIdx.x & 31;
    int nwarps = (gridDim.x * blockDim.x) >> 5;
    const __half2* base = (const __half2*)g_h2h;
    float2 bb = ((const float2*)b)[lane];
    float2 sum = make_float2(0, 0), sq = make_float2(0, 0);

    for (int node = gwarp; node < n; node += nwarps) {
        int e0 = g_rowptr[node], e1 = g_rowptr[node + 1];
        float2 acc = __half22float2(base[(size_t)node * 32 + lane]);
        int e = e0;
        for (; e + 8 <= e1; e += 8) {
            int i0 = g_col[e],     i1 = g_col[e + 1], i2 = g_col[e + 2], i3 = g_col[e + 3];
            int i4 = g_col[e + 4], i5 = g_col[e + 5], i6 = g_col[e + 6], i7 = g_col[e + 7];
            __half2 h0 = base[(size_t)i0 * 32 + lane];
            __half2 h1 = base[(size_t)i1 * 32 + lane];
            __half2 h2 = base[(size_t)i2 * 32 + lane];
            __half2 h3 = base[(size_t)i3 * 32 + lane];
            __half2 h4 = base[(size_t)i4 * 32 + lane];
            __half2 h5 = base[(size_t)i5 * 32 + lane];
            __half2 h6 = base[(size_t)i6 * 32 + lane];
            __half2 h7 = base[(size_t)i7 * 32 + lane];
            float2 f;
            f = __half22float2(h0); acc.x += f.x; acc.y += f.y;
            f = __half22float2(h1); acc.x += f.x; acc.y += f.y;
            f = __half22float2(h2); acc.x += f.x; acc.y += f.y;
            f = __half22float2(h3); acc.x += f.x; acc.y += f.y;
            f = __half22float2(h4); acc.x += f.x; acc.y += f.y;
            f = __half22float2(h5); acc.x += f.x; acc.y += f.y;
            f = __half22float2(h6); acc.x += f.x; acc.y += f.y;
            f = __half22float2(h7); acc.x += f.x; acc.y += f.y;
        }
        for (; e + 4 <= e1; e += 4) {
            int i0 = g_col[e], i1 = g_col[e + 1], i2 = g_col[e + 2], i3 = g_col[e + 3];
            float2 v0 = __half22float2(base[(size_t)i0 * 32 + lane]);
            float2 v1 = __half22float2(base[(size_t)i1 * 32 + lane]);
            float2 v2 = __half22float2(base[(size_t)i2 * 32 + lane]);
            float2 v3 = __half22float2(base[(size_t)i3 * 32 + lane]);
            acc.x += (v0.x + v1.x) + (v2.x + v3.x);
            acc.y += (v0.y + v1.y) + (v2.y + v3.y);
        }
        for (; e < e1; e++) {
            float2 v = __half22float2(base[(size_t)g_col[e] * 32 + lane]);
            acc.x += v.x; acc.y += v.y;
        }
        float d = g_dinv[node];
        float2 o;
        o.x = fmaf(acc.x, d, bb.x); o.y = fmaf(acc.y, d, bb.y);
        ((float2*)out)[(size_t)node * 32 + lane] = o;
        sum.x += o.x; sum.y += o.y;
        sq.x += o.x * o.x; sq.y += o.y * o.y;
    }
    __shared__ float ssum[OUTC], ssq[OUTC];
    __shared__ float sS[OUTC], sT[OUTC];
    int t = threadIdx.x;
    if (t < OUTC) { ssum[t] = 0.f; ssq[t] = 0.f; }
    __syncthreads();
    int c0 = lane * 2;
    atomicAdd(&ssum[c0 + 0], sum.x); atomicAdd(&ssum[c0 + 1], sum.y);
    atomicAdd(&ssq[c0 + 0], sq.x);  atomicAdd(&ssq[c0 + 1], sq.y);
    __syncthreads();
    if (t < OUTC) {
        atomicAdd(&g_stats2[t], ssum[t]);
        atomicAdd(&g_stats2[OUTC + t], ssq[t]);
    }
    __threadfence();
    __shared__ int isLast;
    __syncthreads();
    if (t == 0) isLast = (atomicAdd(&g_ctr2, 1) == (int)gridDim.x - 1);
    __syncthreads();
    if (isLast) {
        if (t < OUTC) {
            float mean = g_stats2[t] * invN;
            float var  = g_stats2[OUTC + t] * invN - mean * mean;
            float sc = gamma[t] * rsqrtf(var + EPS);
            g_stats2[2 * OUTC + t] = sc;
            g_stats2[3 * OUTC + t] = beta[t] - mean * sc;
        }
        __threadfence();
        __syncthreads();
        if (t == 0) atomicExch(&g_flag2, 1);
    }
    if (t == 0) { while (atomicAdd(&g_flag2, 0) == 0) { } }
    __syncthreads();
    if (t < OUTC) { sS[t] = g_stats2[2 * OUTC + t]; sT[t] = g_stats2[3 * OUTC + t]; }
    __syncthreads();
    int gtid = blockIdx.x * blockDim.x + t;
    int stride = gridDim.x * blockDim.x;
    int total4 = n * (OUTC / 4);
    float4* o4 = (float4*)out;
    for (int i = gtid; i < total4; i += stride) {
        float4 v = o4[i];
        int c = (i & 15) * 4;
        v.x = fmaf(v.x, sS[c + 0], sT[c + 0]);
        v.y = fmaf(v.y, sS[c + 1], sT[c + 1]);
        v.z = fmaf(v.z, sS[c + 2], sT[c + 2]);
        v.w = fmaf(v.w, sS[c + 3], sT[c + 3]);
        o4[i] = v;
    }
}

extern "C" void kernel_launch(void* const* d_in, const int* in_sizes, int n_in,
                              void* d_out, int out_size) {
    const float* x      = (const float*)d_in[0];
    const float* W1     = (const float*)d_in[1];
    const float* b1     = (const float*)d_in[2];
    const float* gamma1 = (const float*)d_in[3];
    const float* beta1  = (const float*)d_in[4];
    const float* W2     = (const float*)d_in[5];
    const float* b2     = (const float*)d_in[6];
    const float* gamma2 = (const float*)d_in[7];
    const float* beta2  = (const float*)d_in[8];
    const int*   ei     = (const int*)d_in[9];
    float*       out    = (float*)d_out;

    int N = in_sizes[0] / INC;     // 100000
    int E = in_sizes[9] / 2;       // 1600000
    const int* src = ei;
    const int* dst = ei + E;
    float invN = 1.0f / (float)N;

    const int SMEM1 = 1024 + 2 * 128 * ASTR * 2 + 2 * 128 * ASTR * 2;  // 140288
    const int SMEM2 = 1024 + 2 * 128 * ASTR * 2 + 2 * 64 * ASTR * 2;   // 105472

    static cudaStream_t s2 = nullptr;
    static cudaEvent_t  evC = nullptr, ev1 = nullptr;
    if (!s2) {
        cudaFuncSetAttribute(mmagemm_kernel<128, false, true, false>,
                             cudaFuncAttributeMaxDynamicSharedMemorySize, SMEM1);
        cudaFuncSetAttribute(mmagemm_kernel<64, true, false, true>,
                             cudaFuncAttributeMaxDynamicSharedMemorySize, SMEM2);
        cudaStreamCreateWithFlags(&s2, cudaStreamNonBlocking);
        cudaEventCreateWithFlags(&evC, cudaEventDisableTiming);
        cudaEventCreateWithFlags(&ev1, cudaEventDisableTiming);
    }

    int nb = (N + 1023) / 1024;
    int gblk = (N + 127) / 128;

    // ---- main: degree counts ----
    zero_kernel<<<(N + 255) / 256, 256>>>(N);
    count_kernel<<<(E + 255) / 256, 256>>>(dst, E);
    cudaEventRecord(evC, 0);

    // ---- side: GEMM1 with dinv folded from counts ----
    cudaStreamWaitEvent(s2, evC, 0);
    mmagemm_kernel<128, false, true, false><<<gblk, 256, SMEM1, s2>>>(x, W1, N);
    cudaEventRecord(ev1, s2);

    // ---- main: scan + fill (overlaps GEMM1) ----
    scan1_kernel<<<nb, 1024>>>(N);
    scan3_kernel<<<nb, 1024>>>(N, nb);
    fill_kernel<<<(E + 255) / 256, 256>>>(src, dst, E);

    // ---- join ----
    cudaStreamWaitEvent(0, ev1, 0);

    // aggregate layer 1 (+bias, +BN1 stats+params) -> fp16 a1; single wave (148*6)
    agg128_kernel<<<888, 256>>>(b1, gamma1, beta1, N, invN);
    // h2 = (relu(bn1(a1)) @ W2) * dinv -> fp16
    mmagemm_kernel<64, true, false, true><<<gblk, 256, SMEM2>>>(nullptr, W2, N);
    // aggregate layer 2 into d_out (+BN2 stats+params+apply); single wave (148*4)
    agg64_kernel<<<592, 256>>>(b2, gamma2, beta2, out, N, invN);
}

// round 14
// speedup vs baseline: 1.1652x; 1.0023x over previous
#include <cuda_runtime.h>
#include <cuda_bf16.h>
#include <cuda_fp16.h>
#include <cstdint>

#define NMAX 100000
#define EMAX 1600000
#define INC  128
#define HID  128
#define OUTC 64
#define EPS  1e-5f

// ---------------- scratch (no allocations allowed) ----------------
__device__ int    g_cnt[NMAX];
__device__ int    g_rowptr[NMAX + 1];
__device__ int    g_fill[NMAX];
__device__ int    g_col[EMAX];
__device__ float  g_dinv[NMAX];
__device__ int    g_bsum[128];
__device__ int    g_ctr1, g_ctr2, g_flag2;
__device__ __half g_h1h[(size_t)NMAX * HID];   // (x@W1)*dinv[row], fp16
__device__ __half g_a1h[(size_t)NMAX * HID];   // aggregated layer-1 (pre-BN), fp16
__device__ __half g_h2h[(size_t)NMAX * OUTC];  // (relu(bn1)@W2)*dinv[row], fp16
__device__ float  g_stats1[4 * HID];           // sum | sq | s | t
__device__ float  g_stats2[4 * OUTC];

// ---------------- helpers ----------------
__device__ __forceinline__ uint32_t smem_u32(const void* p) {
    uint32_t a;
    asm("{ .reg .u64 t; cvta.to.shared.u64 t, %1; cvt.u32.u64 %0, t; }" : "=r"(a) : "l"(p));
    return a;
}
__device__ __forceinline__ void ldmatrix_x4(uint32_t* r, uint32_t addr) {
    asm volatile("ldmatrix.sync.aligned.m8n8.x4.shared.b16 {%0,%1,%2,%3}, [%4];"
                 : "=r"(r[0]), "=r"(r[1]), "=r"(r[2]), "=r"(r[3]) : "r"(addr));
}
__device__ __forceinline__ void mma_bf16(float* c, const uint32_t* a, uint32_t b0, uint32_t b1) {
    asm volatile(
        "mma.sync.aligned.m16n8k16.row.col.f32.bf16.bf16.f32 "
        "{%0,%1,%2,%3}, {%4,%5,%6,%7}, {%8,%9}, {%0,%1,%2,%3};"
        : "+f"(c[0]), "+f"(c[1]), "+f"(c[2]), "+f"(c[3])
        : "r"(a[0]), "r"(a[1]), "r"(a[2]), "r"(a[3]), "r"(b0), "r"(b1));
}

// ---------------- init ----------------
__global__ void zero_kernel(int n) {
    int i = blockIdx.x * blockDim.x + threadIdx.x;
    if (i < n)        g_cnt[i] = 0;
    if (i < 4 * HID)  g_stats1[i] = 0.f;
    if (i < 4 * OUTC) g_stats2[i] = 0.f;
    if (i == 0) { g_ctr1 = 0; g_ctr2 = 0; g_flag2 = 0; }
}

// ---------------- degree count ----------------
__global__ void count_kernel(const int* __restrict__ dst, int E) {
    int i = blockIdx.x * blockDim.x + threadIdx.x;
    if (i < E) atomicAdd(&g_cnt[dst[i]], 1);
}

// ---------------- 2-pass parallel scan ----------------
__global__ void scan1_kernel(int n) {
    __shared__ int ws[32];
    int tid = threadIdx.x, lane = tid & 31, w = tid >> 5;
    int i = blockIdx.x * 1024 + tid;
    int v = (i < n) ? g_cnt[i] : 0;
    int x = v;
    #pragma unroll
    for (int off = 1; off < 32; off <<= 1) {
        int y = __shfl_up_sync(0xffffffffu, x, off);
        if (lane >= off) x += y;
    }
    if (lane == 31) ws[w] = x;
    __syncthreads();
    if (w == 0) {
        int y = ws[lane];
        #pragma unroll
        for (int off = 1; off < 32; off <<= 1) {
            int z = __shfl_up_sync(0xffffffffu, y, off);
            if (lane >= off) y += z;
        }
        ws[lane] = y;
    }
    __syncthreads();
    int incl = x + (w ? ws[w - 1] : 0);
    if (i < n) g_fill[i] = incl - v;
    if (tid == 1023) g_bsum[blockIdx.x] = incl;
}
__global__ void scan3_kernel(int n, int nb) {
    __shared__ int excl[128];
    __shared__ int wsum[4];
    int tid = threadIdx.x, lane = tid & 31, w = tid >> 5;
    int xv = 0, vv = 0;
    if (tid < 128) {
        vv = (tid < nb) ? g_bsum[tid] : 0;
        xv = vv;
        #pragma unroll
        for (int off = 1; off < 32; off <<= 1) {
            int y = __shfl_up_sync(0xffffffffu, xv, off);
            if (lane >= off) xv += y;
        }
        if (lane == 31) wsum[w] = xv;
    }
    __syncthreads();
    if (tid < 128) {
        int add = 0;
        #pragma unroll
        for (int j = 0; j < 4; j++) if (j < w) add += wsum[j];
        excl[tid] = xv - vv + add;
    }
    __syncthreads();
    int off = excl[blockIdx.x];
    int i = blockIdx.x * 1024 + tid;
    if (i < n) {
        int c = g_cnt[i];
        int ex = g_fill[i] + off;
        g_fill[i] = ex;
        g_rowptr[i + 1] = ex + c;
        g_dinv[i] = rsqrtf((float)(c + 1));
        if (i == 0) g_rowptr[0] = 0;
    }
}

// ---------------- CSR fill ----------------
__global__ void fill_kernel(const int* __restrict__ src, const int* __restrict__ dst, int E) {
    int i = blockIdx.x * blockDim.x + threadIdx.x;
    if (i < E) {
        int d = dst[i];
        int pos = atomicAdd(&g_fill[d], 1);
        g_col[pos] = src[i];
    }
}

// ---------------- HMMA bf16 GEMM ----------------
#define ASTR 136
template <int TN, bool PRE_BN, bool DINVC, bool DINV>
__global__ __launch_bounds__(256)
void mmagemm_kernel(const float* __restrict__ Aext, const float* __restrict__ W, int M) {
    extern __shared__ char smem[];
    const uint32_t SM_ST = 0;
    const uint32_t A_HI  = 1024;
    const uint32_t A_LO  = A_HI + 128 * ASTR * 2;
    const uint32_t B_HI  = A_LO + 128 * ASTR * 2;
    const uint32_t B_LO  = B_HI + TN * ASTR * 2;

    uint32_t sb = smem_u32(smem);
    int tid = threadIdx.x, wid = tid >> 5, lane = tid & 31;
    int m0 = blockIdx.x * 128;

    if (PRE_BN && tid < 256) {
        float v = (tid < 128) ? g_stats1[2 * HID + tid] : g_stats1[3 * HID + (tid - 128)];
        *(float*)(smem + SM_ST + tid * 4) = v;
    }

    __half* Cout = PRE_BN ? g_h2h : g_h1h;
    const float* s = (const float*)(smem + SM_ST);
    const float* t = s + 128;
    if (PRE_BN) __syncthreads();

    if (PRE_BN) {
        #pragma unroll
        for (int it = 0; it < 8; ++it) {
            int idx = tid + it * 256;
            int row = idx >> 4;
            int c8  = (idx & 15) * 8;
            uint4 u = make_uint4(0, 0, 0, 0);
            if (m0 + row < M) u = *(const uint4*)&g_a1h[(size_t)(m0 + row) * 128 + c8];
            const __half2* hp = (const __half2*)&u;
            uint32_t off = (uint32_t)row * (ASTR * 2) + (uint32_t)c8 * 2;
            #pragma unroll
            for (int j = 0; j < 4; j++) {
                float2 f = __half22float2(hp[j]);
                int k = c8 + 2 * j;
                f.x = fmaxf(fmaf(f.x, s[k + 0], t[k + 0]), 0.f);
                f.y = fmaxf(fmaf(f.y, s[k + 1], t[k + 1]), 0.f);
                __nv_bfloat162 h = __floats2bfloat162_rn(f.x, f.y);
                __nv_bfloat162 l = __floats2bfloat162_rn(f.x - __bfloat162float(h.x),
                                                         f.y - __bfloat162float(h.y));
                *(__nv_bfloat162*)(smem + A_HI + off + 4 * j) = h;
                *(__nv_bfloat162*)(smem + A_LO + off + 4 * j) = l;
            }
        }
    } else {
        #pragma unroll
        for (int it = 0; it < 16; ++it) {
            int idx = tid + it * 256;
            int row = idx >> 5;
            int col = (idx & 31) << 2;
            float4 v = make_float4(0.f, 0.f, 0.f, 0.f);
            if (m0 + row < M) v = *(const float4*)&Aext[(size_t)(m0 + row) * 128 + col];
            __nv_bfloat162 h01 = __floats2bfloat162_rn(v.x, v.y);
            __nv_bfloat162 h23 = __floats2bfloat162_rn(v.z, v.w);
            __nv_bfloat162 l01 = __floats2bfloat162_rn(v.x - __bfloat162float(h01.x),
                                                       v.y - __bfloat162float(h01.y));
            __nv_bfloat162 l23 = __floats2bfloat162_rn(v.z - __bfloat162float(h23.x),
                                                       v.w - __bfloat162float(h23.y));
            uint32_t off = (uint32_t)row * (ASTR * 2) + (uint32_t)col * 2;
            *(__nv_bfloat162*)(smem + A_HI + off)     = h01;
            *(__nv_bfloat162*)(smem + A_HI + off + 4) = h23;
            *(__nv_bfloat162*)(smem + A_LO + off)     = l01;
            *(__nv_bfloat162*)(smem + A_LO + off + 4) = l23;
        }
    }
    for (int idx = tid; idx < 128 * TN; idx += 256) {
        int k = idx / TN, n = idx % TN;
        float w = W[idx];
        __nv_bfloat16 hi = __float2bfloat16_rn(w);
        __nv_bfloat16 lo = __float2bfloat16_rn(w - __bfloat162float(hi));
        uint32_t off = (uint32_t)n * (ASTR * 2) + (uint32_t)k * 2;
        *(__nv_bfloat16*)(smem + B_HI + off) = hi;
        *(__nv_bfloat16*)(smem + B_LO + off) = lo;
    }
    __syncthreads();

    constexpr int WN   = TN / 2;
    constexpr int NSUB = WN / 8;
    int m_base = (wid & 3) * 32;
    int n_base = (wid >> 2) * WN;
    int g = lane >> 2, tt = lane & 3;

    float acc[2][NSUB][4];
    #pragma unroll
    for (int mi = 0; mi < 2; mi++)
        #pragma unroll
        for (int ni = 0; ni < NSUB; ni++)
            #pragma unroll
            for (int j = 0; j < 4; j++) acc[mi][ni][j] = 0.f;

    uint32_t a_row = (uint32_t)(m_base + (lane & 15));
    uint32_t a_cb  = (uint32_t)((lane >> 4) * 8);

    #pragma unroll
    for (int term = 0; term < 3; ++term) {
        uint32_t Abase = sb + ((term == 1) ? A_LO : A_HI);
        uint32_t Bbase = ((term == 2) ? B_LO : B_HI);
        #pragma unroll
        for (int ks = 0; ks < 8; ++ks) {
            int k0 = ks * 16;
            uint32_t af[2][4];
            #pragma unroll
            for (int mi = 0; mi < 2; mi++) {
                uint32_t addr = Abase + (a_row + mi * 16) * (ASTR * 2) + (a_cb + k0) * 2;
                ldmatrix_x4(af[mi], addr);
            }
            const char* brow = smem + Bbase + (uint32_t)(n_base + g) * (ASTR * 2) + (uint32_t)(k0 + 2 * tt) * 2;
            #pragma unroll
            for (int ni = 0; ni < NSUB; ni++) {
                uint32_t b0 = *(const uint32_t*)(brow + ni * 8 * (ASTR * 2));
                uint32_t b1 = *(const uint32_t*)(brow + ni * 8 * (ASTR * 2) + 16);
                mma_bf16(acc[0][ni], af[0], b0, b1);
                mma_bf16(acc[1][ni], af[1], b0, b1);
            }
        }
    }

    #pragma unroll
    for (int mi = 0; mi < 2; mi++) {
        int r0 = m0 + m_base + mi * 16 + g;
        int r1 = r0 + 8;
        float d0 = 1.f, d1 = 1.f;
        if (DINVC) {
            d0 = (r0 < M) ? rsqrtf((float)(g_cnt[r0] + 1)) : 0.f;
            d1 = (r1 < M) ? rsqrtf((float)(g_cnt[r1] + 1)) : 0.f;
        }
        if (DINV) {
            d0 = (r0 < M) ? g_dinv[r0] : 0.f;
            d1 = (r1 < M) ? g_dinv[r1] : 0.f;
        }
        #pragma unroll
        for (int ni = 0; ni < NSUB; ni++) {
            int col = n_base + ni * 8 + 2 * tt;
            if (r0 < M)
                *(__half2*)&Cout[(size_t)r0 * TN + col] =
                    __floats2half2_rn(acc[mi][ni][0] * d0, acc[mi][ni][1] * d0);
            if (r1 < M)
                *(__half2*)&Cout[(size_t)r1 * TN + col] =
                    __floats2half2_rn(acc[mi][ni][2] * d1, acc[mi][ni][3] * d1);
        }
    }
}

// ---------------- aggregation helpers ----------------
__device__ __forceinline__ float4 h4_to_f4(uint2 u) {
    float2 a = __half22float2(*(__half2*)&u.x);
    float2 b = __half22float2(*(__half2*)&u.y);
    return make_float4(a.x, a.y, b.x, b.y);
}
__device__ __forceinline__ void acc4(float4& a, uint2 u) {
    float4 v = h4_to_f4(u);
    a.x += v.x; a.y += v.y; a.z += v.z; a.w += v.w;
}

// ---------------- aggregation, 128 cols; 32-bit indexing; single wave; fused BN1 ----------------
__global__ __launch_bounds__(256, 6)
void agg128_kernel(const float* __restrict__ b, const float* __restrict__ gamma,
                   const float* __restrict__ beta, int n, float invN) {
    int gwarp  = (blockIdx.x * blockDim.x + threadIdx.x) >> 5;
    int lane   = threadIdx.x & 31;
    int nwarps = (gridDim.x * blockDim.x) >> 5;
    const uint2* __restrict__ base = (const uint2*)g_h1h;
    uint2* __restrict__ a1o = (uint2*)g_a1h;
    float4 bb = ((const float4*)b)[lane];
    float4 sum = make_float4(0, 0, 0, 0), sq = make_float4(0, 0, 0, 0);

    for (int node = gwarp; node < n; node += nwarps) {
        int e0 = g_rowptr[node], e1 = g_rowptr[node + 1];
        float4 acc = h4_to_f4(base[node * 32 + lane]);  // self-loop (32-bit idx)
        int e = e0;
        for (; e + 8 <= e1; e += 8) {
            int o0 = g_col[e]     * 32 + lane, o1 = g_col[e + 1] * 32 + lane;
            int o2 = g_col[e + 2] * 32 + lane, o3 = g_col[e + 3] * 32 + lane;
            int o4 = g_col[e + 4] * 32 + lane, o5 = g_col[e + 5] * 32 + lane;
            int o6 = g_col[e + 6] * 32 + lane, o7 = g_col[e + 7] * 32 + lane;
            uint2 v0 = base[o0];
            uint2 v1 = base[o1];
            uint2 v2 = base[o2];
            uint2 v3 = base[o3];
            uint2 v4 = base[o4];
            uint2 v5 = base[o5];
            uint2 v6 = base[o6];
            uint2 v7 = base[o7];
            acc4(acc, v0); acc4(acc, v1); acc4(acc, v2); acc4(acc, v3);
            acc4(acc, v4); acc4(acc, v5); acc4(acc, v6); acc4(acc, v7);
        }
        for (; e + 4 <= e1; e += 4) {
            int o0 = g_col[e]     * 32 + lane, o1 = g_col[e + 1] * 32 + lane;
            int o2 = g_col[e + 2] * 32 + lane, o3 = g_col[e + 3] * 32 + lane;
            uint2 v0 = base[o0];
            uint2 v1 = base[o1];
            uint2 v2 = base[o2];
            uint2 v3 = base[o3];
            acc4(acc, v0); acc4(acc, v1); acc4(acc, v2); acc4(acc, v3);
        }
        for (; e < e1; e++) acc4(acc, base[g_col[e] * 32 + lane]);
        float d = g_dinv[node];
        float4 o;
        o.x = fmaf(acc.x, d, bb.x); o.y = fmaf(acc.y, d, bb.y);
        o.z = fmaf(acc.z, d, bb.z); o.w = fmaf(acc.w, d, bb.w);
        uint2 st;
        *(__half2*)&st.x = __floats2half2_rn(o.x, o.y);
        *(__half2*)&st.y = __floats2half2_rn(o.z, o.w);
        a1o[node * 32 + lane] = st;
        sum.x += o.x; sum.y += o.y; sum.z += o.z; sum.w += o.w;
        sq.x += o.x * o.x; sq.y += o.y * o.y; sq.z += o.z * o.z; sq.w += o.w * o.w;
    }
    __shared__ float ssum[HID], ssq[HID];
    int t = threadIdx.x;
    if (t < HID) { ssum[t] = 0.f; ssq[t] = 0.f; }
    __syncthreads();
    int c0 = lane * 4;
    atomicAdd(&ssum[c0 + 0], sum.x); atomicAdd(&ssum[c0 + 1], sum.y);
    atomicAdd(&ssum[c0 + 2], sum.z); atomicAdd(&ssum[c0 + 3], sum.w);
    atomicAdd(&ssq[c0 + 0], sq.x);  atomicAdd(&ssq[c0 + 1], sq.y);
    atomicAdd(&ssq[c0 + 2], sq.z);  atomicAdd(&ssq[c0 + 3], sq.w);
    __syncthreads();
    if (t < HID) {
        atomicAdd(&g_stats1[t], ssum[t]);
        atomicAdd(&g_stats1[HID + t], ssq[t]);
    }
    __threadfence();
    __shared__ int isLast;
    __syncthreads();
    if (t == 0) isLast = (atomicAdd(&g_ctr1, 1) == (int)gridDim.x - 1);
    __syncthreads();
    if (isLast && t < HID) {
        float mean = g_stats1[t] * invN;
        float var  = g_stats1[HID + t] * invN - mean * mean;
        float sc = gamma[t] * rsqrtf(var + EPS);
        g_stats1[2 * HID + t] = sc;
        g_stats1[3 * HID + t] = beta[t] - mean * sc;
    }
}

// ---------------- aggregation, 64 cols; 32-bit indexing; fused grid-barrier BN2 ----------------
__global__ __launch_bounds__(256, 4)
void agg64_kernel(const float* __restrict__ b, const float* __restrict__ gamma,
                  const float* __restrict__ beta, float* __restrict__ out,
                  int n, float invN) {
    int gwarp  = (blockIdx.x * blockDim.x + threadIdx.x) >> 5;
    int lane   = threadIdx.x & 31;
    int nwarps = (gridDim.x * blockDim.x) >> 5;
    const __half2* __restrict__ base = (const __half2*)g_h2h;
    float2 bb = ((const float2*)b)[lane];
    float2 sum = make_float2(0, 0), sq = make_float2(0, 0);

    for (int node = gwarp; node < n; node += nwarps) {
        int e0 = g_rowptr[node], e1 = g_rowptr[node + 1];
        float2 acc = __half22float2(base[node * 32 + lane]);
        int e = e0;
        for (; e + 8 <= e1; e += 8) {
            int o0 = g_col[e]     * 32 + lane, o1 = g_col[e + 1] * 32 + lane;
            int o2 = g_col[e + 2] * 32 + lane, o3 = g_col[e + 3] * 32 + lane;
            int o4 = g_col[e + 4] * 32 + lane, o5 = g_col[e + 5] * 32 + lane;
            int o6 = g_col[e + 6] * 32 + lane, o7 = g_col[e + 7] * 32 + lane;
            __half2 h0 = base[o0];
            __half2 h1 = base[o1];
            __half2 h2 = base[o2];
            __half2 h3 = base[o3];
            __half2 h4 = base[o4];
            __half2 h5 = base[o5];
            __half2 h6 = base[o6];
            __half2 h7 = base[o7];
            float2 f;
            f = __half22float2(h0); acc.x += f.x; acc.y += f.y;
            f = __half22float2(h1); acc.x += f.x; acc.y += f.y;
            f = __half22float2(h2); acc.x += f.x; acc.y += f.y;
            f = __half22float2(h3); acc.x += f.x; acc.y += f.y;
            f = __half22float2(h4); acc.x += f.x; acc.y += f.y;
            f = __half22float2(h5); acc.x += f.x; acc.y += f.y;
            f = __half22float2(h6); acc.x += f.x; acc.y += f.y;
            f = __half22float2(h7); acc.x += f.x; acc.y += f.y;
        }
        for (; e + 4 <= e1; e += 4) {
            int o0 = g_col[e]     * 32 + lane, o1 = g_col[e + 1] * 32 + lane;
            int o2 = g_col[e + 2] * 32 + lane, o3 = g_col[e + 3] * 32 + lane;
            float2 v0 = __half22float2(base[o0]);
            float2 v1 = __half22float2(base[o1]);
            float2 v2 = __half22float2(base[o2]);
            float2 v3 = __half22float2(base[o3]);
            acc.x += (v0.x + v1.x) + (v2.x + v3.x);
            acc.y += (v0.y + v1.y) + (v2.y + v3.y);
        }
        for (; e < e1; e++) {
            float2 v = __half22float2(base[g_col[e] * 32 + lane]);
            acc.x += v.x; acc.y += v.y;
        }
        float d = g_dinv[node];
        float2 o;
        o.x = fmaf(acc.x, d, bb.x); o.y = fmaf(acc.y, d, bb.y);
        ((float2*)out)[node * 32 + lane] = o;
        sum.x += o.x; sum.y += o.y;
        sq.x += o.x * o.x; sq.y += o.y * o.y;
    }
    __shared__ float ssum[OUTC], ssq[OUTC];
    __shared__ float sS[OUTC], sT[OUTC];
    int t = threadIdx.x;
    if (t < OUTC) { ssum[t] = 0.f; ssq[t] = 0.f; }
    __syncthreads();
    int c0 = lane * 2;
    atomicAdd(&ssum[c0 + 0], sum.x); atomicAdd(&ssum[c0 + 1], sum.y);
    atomicAdd(&ssq[c0 + 0], sq.x);  atomicAdd(&ssq[c0 + 1], sq.y);
    __syncthreads();
    if (t < OUTC) {
        atomicAdd(&g_stats2[t], ssum[t]);
        atomicAdd(&g_stats2[OUTC + t], ssq[t]);
    }
    __threadfence();
    __shared__ int isLast;
    __syncthreads();
    if (t == 0) isLast = (atomicAdd(&g_ctr2, 1) == (int)gridDim.x - 1);
    __syncthreads();
    if (isLast) {
        if (t < OUTC) {
            float mean = g_stats2[t] * invN;
            float var  = g_stats2[OUTC + t] * invN - mean * mean;
            float sc = gamma[t] * rsqrtf(var + EPS);
            g_stats2[2 * OUTC + t] = sc;
            g_stats2[3 * OUTC + t] = beta[t] - mean * sc;
        }
        __threadfence();
        __syncthreads();
        if (t == 0) atomicExch(&g_flag2, 1);
    }
    if (t == 0) { while (atomicAdd(&g_flag2, 0) == 0) { } }
    __syncthreads();
    if (t < OUTC) { sS[t] = g_stats2[2 * OUTC + t]; sT[t] = g_stats2[3 * OUTC + t]; }
    __syncthreads();
    int gtid = blockIdx.x * blockDim.x + t;
    int stride = gridDim.x * blockDim.x;
    int total4 = n * (OUTC / 4);
    float4* o4 = (float4*)out;
    for (int i = gtid; i < total4; i += stride) {
        float4 v = o4[i];
        int c = (i & 15) * 4;
        v.x = fmaf(v.x, sS[c + 0], sT[c + 0]);
        v.y = fmaf(v.y, sS[c + 1], sT[c + 1]);
        v.z = fmaf(v.z, sS[c + 2], sT[c + 2]);
        v.w = fmaf(v.w, sS[c + 3], sT[c + 3]);
        o4[i] = v;
    }
}

extern "C" void kernel_launch(void* const* d_in, const int* in_sizes, int n_in,
                              void* d_out, int out_size) {
    const float* x      = (const float*)d_in[0];
    const float* W1     = (const float*)d_in[1];
    const float* b1     = (const float*)d_in[2];
    const float* gamma1 = (const float*)d_in[3];
    const float* beta1  = (const float*)d_in[4];
    const float* W2     = (const float*)d_in[5];
    const float* b2     = (const float*)d_in[6];
    const float* gamma2 = (const float*)d_in[7];
    const float* beta2  = (const float*)d_in[8];
    const int*   ei     = (const int*)d_in[9];
    float*       out    = (float*)d_out;

    int N = in_sizes[0] / INC;     // 100000
    int E = in_sizes[9] / 2;       // 1600000
    const int* src = ei;
    const int* dst = ei + E;
    float invN = 1.0f / (float)N;

    const int SMEM1 = 1024 + 2 * 128 * ASTR * 2 + 2 * 128 * ASTR * 2;  // 140288
    const int SMEM2 = 1024 + 2 * 128 * ASTR * 2 + 2 * 64 * ASTR * 2;   // 105472

    static cudaStream_t s2 = nullptr;
    static cudaEvent_t  evC = nullptr, ev1 = nullptr;
    if (!s2) {
        cudaFuncSetAttribute(mmagemm_kernel<128, false, true, false>,
                             cudaFuncAttributeMaxDynamicSharedMemorySize, SMEM1);
        cudaFuncSetAttribute(mmagemm_kernel<64, true, false, true>,
                             cudaFuncAttributeMaxDynamicSharedMemorySize, SMEM2);
        cudaStreamCreateWithFlags(&s2, cudaStreamNonBlocking);
        cudaEventCreateWithFlags(&evC, cudaEventDisableTiming);
        cudaEventCreateWithFlags(&ev1, cudaEventDisableTiming);
    }

    int nb = (N + 1023) / 1024;
    int gblk = (N + 127) / 128;

    // ---- main: degree counts ----
    zero_kernel<<<(N + 255) / 256, 256>>>(N);
    count_kernel<<<(E + 255) / 256, 256>>>(dst, E);
    cudaEventRecord(evC, 0);

    // ---- side: GEMM1 with dinv folded from counts ----
    cudaStreamWaitEvent(s2, evC, 0);
    mmagemm_kernel<128, false, true, false><<<gblk, 256, SMEM1, s2>>>(x, W1, N);
    cudaEventRecord(ev1, s2);

    // ---- main: scan + fill (overlaps GEMM1) ----
    scan1_kernel<<<nb, 1024>>>(N);
    scan3_kernel<<<nb, 1024>>>(N, nb);
    fill_kernel<<<(E + 255) / 256, 256>>>(src, dst, E);

    // ---- join ----
    cudaStreamWaitEvent(0, ev1, 0);

    // aggregate layer 1 (+bias, +BN1 stats+params) -> fp16 a1; single wave (148*6)
    agg128_kernel<<<888, 256>>>(b1, gamma1, beta1, N, invN);
    // h2 = (relu(bn1(a1)) @ W2) * dinv -> fp16
    mmagemm_kernel<64, true, false, true><<<gblk, 256, SMEM2>>>(nullptr, W2, N);
    // aggregate layer 2 into d_out (+BN2 stats+params+apply); single wave (148*4)
    agg64_kernel<<<592, 256>>>(b2, gamma2, beta2, out, N, invN);
}

// round 15
// speedup vs baseline: 1.1729x; 1.0067x over previous
#include <cuda_runtime.h>
#include <cuda_bf16.h>
#include <cuda_fp16.h>
#include <cstdint>

#define NMAX 100000
#define EMAX 1600000
#define INC  128
#define HID  128
#define OUTC 64
#define EPS  1e-5f

// ---------------- scratch (no allocations allowed) ----------------
__device__ int    g_cnt[NMAX];
__device__ int    g_rowptr[NMAX + 1];
__device__ int    g_fill[NMAX];
__device__ int    g_col[EMAX];
__device__ float  g_dinv[NMAX];
__device__ int    g_bsum[128];
__device__ int    g_ctr1, g_ctr2, g_flag2;
__device__ __half g_h1h[(size_t)NMAX * HID];   // (x@W1)*dinv[row], fp16
__device__ __half g_a1h[(size_t)NMAX * HID];   // aggregated layer-1 (pre-BN), fp16
__device__ __half g_h2h[(size_t)NMAX * OUTC];  // (relu(bn1)@W2)*dinv[row], fp16
__device__ float  g_stats1[4 * HID];           // sum | sq | s | t
__device__ float  g_stats2[4 * OUTC];

// ---------------- helpers ----------------
__device__ __forceinline__ uint32_t smem_u32(const void* p) {
    uint32_t a;
    asm("{ .reg .u64 t; cvta.to.shared.u64 t, %1; cvt.u32.u64 %0, t; }" : "=r"(a) : "l"(p));
    return a;
}
__device__ __forceinline__ void ldmatrix_x4(uint32_t* r, uint32_t addr) {
    asm volatile("ldmatrix.sync.aligned.m8n8.x4.shared.b16 {%0,%1,%2,%3}, [%4];"
                 : "=r"(r[0]), "=r"(r[1]), "=r"(r[2]), "=r"(r[3]) : "r"(addr));
}
__device__ __forceinline__ void mma_bf16(float* c, const uint32_t* a, uint32_t b0, uint32_t b1) {
    asm volatile(
        "mma.sync.aligned.m16n8k16.row.col.f32.bf16.bf16.f32 "
        "{%0,%1,%2,%3}, {%4,%5,%6,%7}, {%8,%9}, {%0,%1,%2,%3};"
        : "+f"(c[0]), "+f"(c[1]), "+f"(c[2]), "+f"(c[3])
        : "r"(a[0]), "r"(a[1]), "r"(a[2]), "r"(a[3]), "r"(b0), "r"(b1));
}

// ---------------- init ----------------
__global__ void zero_kernel(int n) {
    int i = blockIdx.x * blockDim.x + threadIdx.x;
    if (i < n)        g_cnt[i] = 0;
    if (i < 4 * HID)  g_stats1[i] = 0.f;
    if (i < 4 * OUTC) g_stats2[i] = 0.f;
    if (i == 0) { g_ctr1 = 0; g_ctr2 = 0; g_flag2 = 0; }
}

// ---------------- degree count: int4, 4 edges/thread (MLP-4 atomics) ----------------
__global__ void count_kernel(const int* __restrict__ dst, int E) {
    int E4 = E >> 2;
    int i = blockIdx.x * blockDim.x + threadIdx.x;
    if (i < E4) {
        int4 d = ((const int4*)dst)[i];
        atomicAdd(&g_cnt[d.x], 1);
        atomicAdd(&g_cnt[d.y], 1);
        atomicAdd(&g_cnt[d.z], 1);
        atomicAdd(&g_cnt[d.w], 1);
    }
    // tail (E not multiple of 4)
    int tbase = E4 << 2;
    int ti = tbase + i;
    if (i < (E - tbase)) atomicAdd(&g_cnt[dst[ti]], 1);
}

// ---------------- 2-pass parallel scan ----------------
__global__ void scan1_kernel(int n) {
    __shared__ int ws[32];
    int tid = threadIdx.x, lane = tid & 31, w = tid >> 5;
    int i = blockIdx.x * 1024 + tid;
    int v = (i < n) ? g_cnt[i] : 0;
    int x = v;
    #pragma unroll
    for (int off = 1; off < 32; off <<= 1) {
        int y = __shfl_up_sync(0xffffffffu, x, off);
        if (lane >= off) x += y;
    }
    if (lane == 31) ws[w] = x;
    __syncthreads();
    if (w == 0) {
        int y = ws[lane];
        #pragma unroll
        for (int off = 1; off < 32; off <<= 1) {
            int z = __shfl_up_sync(0xffffffffu, y, off);
            if (lane >= off) y += z;
        }
        ws[lane] = y;
    }
    __syncthreads();
    int incl = x + (w ? ws[w - 1] : 0);
    if (i < n) g_fill[i] = incl - v;
    if (tid == 1023) g_bsum[blockIdx.x] = incl;
}
__global__ void scan3_kernel(int n, int nb) {
    __shared__ int excl[128];
    __shared__ int wsum[4];
    int tid = threadIdx.x, lane = tid & 31, w = tid >> 5;
    int xv = 0, vv = 0;
    if (tid < 128) {
        vv = (tid < nb) ? g_bsum[tid] : 0;
        xv = vv;
        #pragma unroll
        for (int off = 1; off < 32; off <<= 1) {
            int y = __shfl_up_sync(0xffffffffu, xv, off);
            if (lane >= off) xv += y;
        }
        if (lane == 31) wsum[w] = xv;
    }
    __syncthreads();
    if (tid < 128) {
        int add = 0;
        #pragma unroll
        for (int j = 0; j < 4; j++) if (j < w) add += wsum[j];
        excl[tid] = xv - vv + add;
    }
    __syncthreads();
    int off = excl[blockIdx.x];
    int i = blockIdx.x * 1024 + tid;
    if (i < n) {
        int c = g_cnt[i];
        int ex = g_fill[i] + off;
        g_fill[i] = ex;
        g_rowptr[i + 1] = ex + c;
        g_dinv[i] = rsqrtf((float)(c + 1));
        if (i == 0) g_rowptr[0] = 0;
    }
}

// ---------------- CSR fill: int4, 4 edges/thread (MLP-4 atomic returns) ----------------
__global__ void fill_kernel(const int* __restrict__ src, const int* __restrict__ dst, int E) {
    int E4 = E >> 2;
    int i = blockIdx.x * blockDim.x + threadIdx.x;
    if (i < E4) {
        int4 d = ((const int4*)dst)[i];
        int4 s = ((const int4*)src)[i];
        int p0 = atomicAdd(&g_fill[d.x], 1);
        int p1 = atomicAdd(&g_fill[d.y], 1);
        int p2 = atomicAdd(&g_fill[d.z], 1);
        int p3 = atomicAdd(&g_fill[d.w], 1);
        g_col[p0] = s.x;
        g_col[p1] = s.y;
        g_col[p2] = s.z;
        g_col[p3] = s.w;
    }
    int tbase = E4 << 2;
    int ti = tbase + i;
    if (i < (E - tbase)) {
        int pos = atomicAdd(&g_fill[dst[ti]], 1);
        g_col[pos] = src[ti];
    }
}

// ---------------- HMMA bf16 GEMM ----------------
#define ASTR 136
template <int TN, bool PRE_BN, bool DINVC, bool DINV>
__global__ __launch_bounds__(256)
void mmagemm_kernel(const float* __restrict__ Aext, const float* __restrict__ W, int M) {
    extern __shared__ char smem[];
    const uint32_t SM_ST = 0;
    const uint32_t A_HI  = 1024;
    const uint32_t A_LO  = A_HI + 128 * ASTR * 2;
    const uint32_t B_HI  = A_LO + 128 * ASTR * 2;
    const uint32_t B_LO  = B_HI + TN * ASTR * 2;

    uint32_t sb = smem_u32(smem);
    int tid = threadIdx.x, wid = tid >> 5, lane = tid & 31;
    int m0 = blockIdx.x * 128;

    if (PRE_BN && tid < 256) {
        float v = (tid < 128) ? g_stats1[2 * HID + tid] : g_stats1[3 * HID + (tid - 128)];
        *(float*)(smem + SM_ST + tid * 4) = v;
    }

    __half* Cout = PRE_BN ? g_h2h : g_h1h;
    const float* s = (const float*)(smem + SM_ST);
    const float* t = s + 128;
    if (PRE_BN) __syncthreads();

    if (PRE_BN) {
        #pragma unroll
        for (int it = 0; it < 8; ++it) {
            int idx = tid + it * 256;
            int row = idx >> 4;
            int c8  = (idx & 15) * 8;
            uint4 u = make_uint4(0, 0, 0, 0);
            if (m0 + row < M) u = *(const uint4*)&g_a1h[(size_t)(m0 + row) * 128 + c8];
            const __half2* hp = (const __half2*)&u;
            uint32_t off = (uint32_t)row * (ASTR * 2) + (uint32_t)c8 * 2;
            #pragma unroll
            for (int j = 0; j < 4; j++) {
                float2 f = __half22float2(hp[j]);
                int k = c8 + 2 * j;
                f.x = fmaxf(fmaf(f.x, s[k + 0], t[k + 0]), 0.f);
                f.y = fmaxf(fmaf(f.y, s[k + 1], t[k + 1]), 0.f);
                __nv_bfloat162 h = __floats2bfloat162_rn(f.x, f.y);
                __nv_bfloat162 l = __floats2bfloat162_rn(f.x - __bfloat162float(h.x),
                                                         f.y - __bfloat162float(h.y));
                *(__nv_bfloat162*)(smem + A_HI + off + 4 * j) = h;
                *(__nv_bfloat162*)(smem + A_LO + off + 4 * j) = l;
            }
        }
    } else {
        #pragma unroll
        for (int it = 0; it < 16; ++it) {
            int idx = tid + it * 256;
            int row = idx >> 5;
            int col = (idx & 31) << 2;
            float4 v = make_float4(0.f, 0.f, 0.f, 0.f);
            if (m0 + row < M) v = *(const float4*)&Aext[(size_t)(m0 + row) * 128 + col];
            __nv_bfloat162 h01 = __floats2bfloat162_rn(v.x, v.y);
            __nv_bfloat162 h23 = __floats2bfloat162_rn(v.z, v.w);
            __nv_bfloat162 l01 = __floats2bfloat162_rn(v.x - __bfloat162float(h01.x),
                                                       v.y - __bfloat162float(h01.y));
            __nv_bfloat162 l23 = __floats2bfloat162_rn(v.z - __bfloat162float(h23.x),
                                                       v.w - __bfloat162float(h23.y));
            uint32_t off = (uint32_t)row * (ASTR * 2) + (uint32_t)col * 2;
            *(__nv_bfloat162*)(smem + A_HI + off)     = h01;
            *(__nv_bfloat162*)(smem + A_HI + off + 4) = h23;
            *(__nv_bfloat162*)(smem + A_LO + off)     = l01;
            *(__nv_bfloat162*)(smem + A_LO + off + 4) = l23;
        }
    }
    for (int idx = tid; idx < 128 * TN; idx += 256) {
        int k = idx / TN, n = idx % TN;
        float w = W[idx];
        __nv_bfloat16 hi = __float2bfloat16_rn(w);
        __nv_bfloat16 lo = __float2bfloat16_rn(w - __bfloat162float(hi));
        uint32_t off = (uint32_t)n * (ASTR * 2) + (uint32_t)k * 2;
        *(__nv_bfloat16*)(smem + B_HI + off) = hi;
        *(__nv_bfloat16*)(smem + B_LO + off) = lo;
    }
    __syncthreads();

    constexpr int WN   = TN / 2;
    constexpr int NSUB = WN / 8;
    int m_base = (wid & 3) * 32;
    int n_base = (wid >> 2) * WN;
    int g = lane >> 2, tt = lane & 3;

    float acc[2][NSUB][4];
    #pragma unroll
    for (int mi = 0; mi < 2; mi++)
        #pragma unroll
        for (int ni = 0; ni < NSUB; ni++)
            #pragma unroll
            for (int j = 0; j < 4; j++) acc[mi][ni][j] = 0.f;

    uint32_t a_row = (uint32_t)(m_base + (lane & 15));
    uint32_t a_cb  = (uint32_t)((lane >> 4) * 8);

    #pragma unroll
    for (int term = 0; term < 3; ++term) {
        uint32_t Abase = sb + ((term == 1) ? A_LO : A_HI);
        uint32_t Bbase = ((term == 2) ? B_LO : B_HI);
        #pragma unroll
        for (int ks = 0; ks < 8; ++ks) {
            int k0 = ks * 16;
            uint32_t af[2][4];
            #pragma unroll
            for (int mi = 0; mi < 2; mi++) {
                uint32_t addr = Abase + (a_row + mi * 16) * (ASTR * 2) + (a_cb + k0) * 2;
                ldmatrix_x4(af[mi], addr);
            }
            const char* brow = smem + Bbase + (uint32_t)(n_base + g) * (ASTR * 2) + (uint32_t)(k0 + 2 * tt) * 2;
            #pragma unroll
            for (int ni = 0; ni < NSUB; ni++) {
                uint32_t b0 = *(const uint32_t*)(brow + ni * 8 * (ASTR * 2));
                uint32_t b1 = *(const uint32_t*)(brow + ni * 8 * (ASTR * 2) + 16);
                mma_bf16(acc[0][ni], af[0], b0, b1);
                mma_bf16(acc[1][ni], af[1], b0, b1);
            }
        }
    }

    #pragma unroll
    for (int mi = 0; mi < 2; mi++) {
        int r0 = m0 + m_base + mi * 16 + g;
        int r1 = r0 + 8;
        float d0 = 1.f, d1 = 1.f;
        if (DINVC) {
            d0 = (r0 < M) ? rsqrtf((float)(g_cnt[r0] + 1)) : 0.f;
            d1 = (r1 < M) ? rsqrtf((float)(g_cnt[r1] + 1)) : 0.f;
        }
        if (DINV) {
            d0 = (r0 < M) ? g_dinv[r0] : 0.f;
            d1 = (r1 < M) ? g_dinv[r1] : 0.f;
        }
        #pragma unroll
        for (int ni = 0; ni < NSUB; ni++) {
            int col = n_base + ni * 8 + 2 * tt;
            if (r0 < M)
                *(__half2*)&Cout[(size_t)r0 * TN + col] =
                    __floats2half2_rn(acc[mi][ni][0] * d0, acc[mi][ni][1] * d0);
            if (r1 < M)
                *(__half2*)&Cout[(size_t)r1 * TN + col] =
                    __floats2half2_rn(acc[mi][ni][2] * d1, acc[mi][ni][3] * d1);
        }
    }
}

// ---------------- aggregation helpers ----------------
__device__ __forceinline__ float4 h4_to_f4(uint2 u) {
    float2 a = __half22float2(*(__half2*)&u.x);
    float2 b = __half22float2(*(__half2*)&u.y);
    return make_float4(a.x, a.y, b.x, b.y);
}
__device__ __forceinline__ void acc4(float4& a, uint2 u) {
    float4 v = h4_to_f4(u);
    a.x += v.x; a.y += v.y; a.z += v.z; a.w += v.w;
}

// ---------------- aggregation, 128 cols; single wave; fused BN1 ----------------
__global__ __launch_bounds__(256, 6)
void agg128_kernel(const float* __restrict__ b, const float* __restrict__ gamma,
                   const float* __restrict__ beta, int n, float invN) {
    int gwarp  = (blockIdx.x * blockDim.x + threadIdx.x) >> 5;
    int lane   = threadIdx.x & 31;
    int nwarps = (gridDim.x * blockDim.x) >> 5;
    const uint2* __restrict__ base = (const uint2*)g_h1h;
    uint2* __restrict__ a1o = (uint2*)g_a1h;
    float4 bb = ((const float4*)b)[lane];
    float4 sum = make_float4(0, 0, 0, 0), sq = make_float4(0, 0, 0, 0);

    for (int node = gwarp; node < n; node += nwarps) {
        int e0 = g_rowptr[node], e1 = g_rowptr[node + 1];
        float4 acc = h4_to_f4(base[node * 32 + lane]);  // self-loop
        int e = e0;
        for (; e + 8 <= e1; e += 8) {
            int o0 = g_col[e]     * 32 + lane, o1 = g_col[e + 1] * 32 + lane;
            int o2 = g_col[e + 2] * 32 + lane, o3 = g_col[e + 3] * 32 + lane;
            int o4 = g_col[e + 4] * 32 + lane, o5 = g_col[e + 5] * 32 + lane;
            int o6 = g_col[e + 6] * 32 + lane, o7 = g_col[e + 7] * 32 + lane;
            uint2 v0 = base[o0];
            uint2 v1 = base[o1];
            uint2 v2 = base[o2];
            uint2 v3 = base[o3];
            uint2 v4 = base[o4];
            uint2 v5 = base[o5];
            uint2 v6 = base[o6];
            uint2 v7 = base[o7];
            acc4(acc, v0); acc4(acc, v1); acc4(acc, v2); acc4(acc, v3);
            acc4(acc, v4); acc4(acc, v5); acc4(acc, v6); acc4(acc, v7);
        }
        for (; e + 4 <= e1; e += 4) {
            int o0 = g_col[e]     * 32 + lane, o1 = g_col[e + 1] * 32 + lane;
            int o2 = g_col[e + 2] * 32 + lane, o3 = g_col[e + 3] * 32 + lane;
            uint2 v0 = base[o0];
            uint2 v1 = base[o1];
            uint2 v2 = base[o2];
            uint2 v3 = base[o3];
            acc4(acc, v0); acc4(acc, v1); acc4(acc, v2); acc4(acc, v3);
        }
        for (; e < e1; e++) acc4(acc, base[g_col[e] * 32 + lane]);
        float d = g_dinv[node];
        float4 o;
        o.x = fmaf(acc.x, d, bb.x); o.y = fmaf(acc.y, d, bb.y);
        o.z = fmaf(acc.z, d, bb.z); o.w = fmaf(acc.w, d, bb.w);
        uint2 st;
        *(__half2*)&st.x = __floats2half2_rn(o.x, o.y);
        *(__half2*)&st.y = __floats2half2_rn(o.z, o.w);
        a1o[node * 32 + lane] = st;
        sum.x += o.x; sum.y += o.y; sum.z += o.z; sum.w += o.w;
        sq.x += o.x * o.x; sq.y += o.y * o.y; sq.z += o.z * o.z; sq.w += o.w * o.w;
    }
    __shared__ float ssum[HID], ssq[HID];
    int t = threadIdx.x;
    if (t < HID) { ssum[t] = 0.f; ssq[t] = 0.f; }
    __syncthreads();
    int c0 = lane * 4;
    atomicAdd(&ssum[c0 + 0], sum.x); atomicAdd(&ssum[c0 + 1], sum.y);
    atomicAdd(&ssum[c0 + 2], sum.z); atomicAdd(&ssum[c0 + 3], sum.w);
    atomicAdd(&ssq[c0 + 0], sq.x);  atomicAdd(&ssq[c0 + 1], sq.y);
    atomicAdd(&ssq[c0 + 2], sq.z);  atomicAdd(&ssq[c0 + 3], sq.w);
    __syncthreads();
    if (t < HID) {
        atomicAdd(&g_stats1[t], ssum[t]);
        atomicAdd(&g_stats1[HID + t], ssq[t]);
    }
    __threadfence();
    __shared__ int isLast;
    __syncthreads();
    if (t == 0) isLast = (atomicAdd(&g_ctr1, 1) == (int)gridDim.x - 1);
    __syncthreads();
    if (isLast && t < HID) {
        float mean = g_stats1[t] * invN;
        float var  = g_stats1[HID + t] * invN - mean * mean;
        float sc = gamma[t] * rsqrtf(var + EPS);
        g_stats1[2 * HID + t] = sc;
        g_stats1[3 * HID + t] = beta[t] - mean * sc;
    }
}

// ---------------- aggregation, 64 cols; fused grid-barrier BN2 ----------------
__global__ __launch_bounds__(256, 4)
void agg64_kernel(const float* __restrict__ b, const float* __restrict__ gamma,
                  const float* __restrict__ beta, float* __restrict__ out,
                  int n, float invN) {
    int gwarp  = (blockIdx.x * blockDim.x + threadIdx.x) >> 5;
    int lane   = threadIdx.x & 31;
    int nwarps = (gridDim.x * blockDim.x) >> 5;
    const __half2* __restrict__ base = (const __half2*)g_h2h;
    float2 bb = ((const float2*)b)[lane];
    float2 sum = make_float2(0, 0), sq = make_float2(0, 0);

    for (int node = gwarp; node < n; node += nwarps) {
        int e0 = g_rowptr[node], e1 = g_rowptr[node + 1];
        float2 acc = __half22float2(base[node * 32 + lane]);
        int e = e0;
        for (; e + 8 <= e1; e += 8) {
            int o0 = g_col[e]     * 32 + lane, o1 = g_col[e + 1] * 32 + lane;
            int o2 = g_col[e + 2] * 32 + lane, o3 = g_col[e + 3] * 32 + lane;
            int o4 = g_col[e + 4] * 32 + lane, o5 = g_col[e + 5] * 32 + lane;
            int o6 = g_col[e + 6] * 32 + lane, o7 = g_col[e + 7] * 32 + lane;
            __half2 h0 = base[o0];
            __half2 h1 = base[o1];
            __half2 h2 = base[o2];
            __half2 h3 = base[o3];
            __half2 h4 = base[o4];
            __half2 h5 = base[o5];
            __half2 h6 = base[o6];
            __half2 h7 = base[o7];
            float2 f;
            f = __half22float2(h0); acc.x += f.x; acc.y += f.y;
            f = __half22float2(h1); acc.x += f.x; acc.y += f.y;
            f = __half22float2(h2); acc.x += f.x; acc.y += f.y;
            f = __half22float2(h3); acc.x += f.x; acc.y += f.y;
            f = __half22float2(h4); acc.x += f.x; acc.y += f.y;
            f = __half22float2(h5); acc.x += f.x; acc.y += f.y;
            f = __half22float2(h6); acc.x += f.x; acc.y += f.y;
            f = __half22float2(h7); acc.x += f.x; acc.y += f.y;
        }
        for (; e + 4 <= e1; e += 4) {
            int o0 = g_col[e]     * 32 + lane, o1 = g_col[e + 1] * 32 + lane;
            int o2 = g_col[e + 2] * 32 + lane, o3 = g_col[e + 3] * 32 + lane;
            float2 v0 = __half22float2(base[o0]);
            float2 v1 = __half22float2(base[o1]);
            float2 v2 = __half22float2(base[o2]);
            float2 v3 = __half22float2(base[o3]);
            acc.x += (v0.x + v1.x) + (v2.x + v3.x);
            acc.y += (v0.y + v1.y) + (v2.y + v3.y);
        }
        for (; e < e1; e++) {
            float2 v = __half22float2(base[g_col[e] * 32 + lane]);
            acc.x += v.x; acc.y += v.y;
        }
        float d = g_dinv[node];
        float2 o;
        o.x = fmaf(acc.x, d, bb.x); o.y = fmaf(acc.y, d, bb.y);
        ((float2*)out)[node * 32 + lane] = o;
        sum.x += o.x; sum.y += o.y;
        sq.x += o.x * o.x; sq.y += o.y * o.y;
    }
    __shared__ float ssum[OUTC], ssq[OUTC];
    __shared__ float sS[OUTC], sT[OUTC];
    int t = threadIdx.x;
    if (t < OUTC) { ssum[t] = 0.f; ssq[t] = 0.f; }
    __syncthreads();
    int c0 = lane * 2;
    atomicAdd(&ssum[c0 + 0], sum.x); atomicAdd(&ssum[c0 + 1], sum.y);
    atomicAdd(&ssq[c0 + 0], sq.x);  atomicAdd(&ssq[c0 + 1], sq.y);
    __syncthreads();
    if (t < OUTC) {
        atomicAdd(&g_stats2[t], ssum[t]);
        atomicAdd(&g_stats2[OUTC + t], ssq[t]);
    }
    __threadfence();
    __shared__ int isLast;
    __syncthreads();
    if (t == 0) isLast = (atomicAdd(&g_ctr2, 1) == (int)gridDim.x - 1);
    __syncthreads();
    if (isLast) {
        if (t < OUTC) {
            float mean = g_stats2[t] * invN;
            float var  = g_stats2[OUTC + t] * invN - mean * mean;
            float sc = gamma[t] * rsqrtf(var + EPS);
            g_stats2[2 * OUTC + t] = sc;
            g_stats2[3 * OUTC + t] = beta[t] - mean * sc;
        }
        __threadfence();
        __syncthreads();
        if (t == 0) atomicExch(&g_flag2, 1);
    }
    if (t == 0) { while (atomicAdd(&g_flag2, 0) == 0) { } }
    __syncthreads();
    if (t < OUTC) { sS[t] = g_stats2[2 * OUTC + t]; sT[t] = g_stats2[3 * OUTC + t]; }
    __syncthreads();
    int gtid = blockIdx.x * blockDim.x + t;
    int stride = gridDim.x * blockDim.x;
    int total4 = n * (OUTC / 4);
    float4* o4 = (float4*)out;
    for (int i = gtid; i < total4; i += stride) {
        float4 v = o4[i];
        int c = (i & 15) * 4;
        v.x = fmaf(v.x, sS[c + 0], sT[c + 0]);
        v.y = fmaf(v.y, sS[c + 1], sT[c + 1]);
        v.z = fmaf(v.z, sS[c + 2], sT[c + 2]);
        v.w = fmaf(v.w, sS[c + 3], sT[c + 3]);
        o4[i] = v;
    }
}

extern "C" void kernel_launch(void* const* d_in, const int* in_sizes, int n_in,
                              void* d_out, int out_size) {
    const float* x      = (const float*)d_in[0];
    const float* W1     = (const float*)d_in[1];
    const float* b1     = (const float*)d_in[2];
    const float* gamma1 = (const float*)d_in[3];
    const float* beta1  = (const float*)d_in[4];
    const float* W2     = (const float*)d_in[5];
    const float* b2     = (const float*)d_in[6];
    const float* gamma2 = (const float*)d_in[7];
    const float* beta2  = (const float*)d_in[8];
    const int*   ei     = (const int*)d_in[9];
    float*       out    = (float*)d_out;

    int N = in_sizes[0] / INC;     // 100000
    int E = in_sizes[9] / 2;       // 1600000
    const int* src = ei;
    const int* dst = ei + E;
    float invN = 1.0f / (float)N;

    const int SMEM1 = 1024 + 2 * 128 * ASTR * 2 + 2 * 128 * ASTR * 2;  // 140288
    const int SMEM2 = 1024 + 2 * 128 * ASTR * 2 + 2 * 64 * ASTR * 2;   // 105472

    static cudaStream_t s2 = nullptr;
    static cudaEvent_t  evC = nullptr, ev1 = nullptr;
    if (!s2) {
        cudaFuncSetAttribute(mmagemm_kernel<128, false, true, false>,
                             cudaFuncAttributeMaxDynamicSharedMemorySize, SMEM1);
        cudaFuncSetAttribute(mmagemm_kernel<64, true, false, true>,
                             cudaFuncAttributeMaxDynamicSharedMemorySize, SMEM2);
        cudaStreamCreateWithFlags(&s2, cudaStreamNonBlocking);
        cudaEventCreateWithFlags(&evC, cudaEventDisableTiming);
        cudaEventCreateWithFlags(&ev1, cudaEventDisableTiming);
    }

    int nb = (N + 1023) / 1024;
    int gblk = (N + 127) / 128;
    int e4blk = (E / 4 + 255) / 256;

    // ---- main: degree counts (int4, MLP-4) ----
    zero_kernel<<<(N + 255) / 256, 256>>>(N);
    count_kernel<<<e4blk, 256>>>(dst, E);
    cudaEventRecord(evC, 0);

    // ---- side: GEMM1 with dinv folded from counts ----
    cudaStreamWaitEvent(s2, evC, 0);
    mmagemm_kernel<128, false, true, false><<<gblk, 256, SMEM1, s2>>>(x, W1, N);
    cudaEventRecord(ev1, s2);

    // ---- main: scan + fill (int4, MLP-4), overlaps GEMM1 ----
    scan1_kernel<<<nb, 1024>>>(N);
    scan3_kernel<<<nb, 1024>>>(N, nb);
    fill_kernel<<<e4blk, 256>>>(src, dst, E);

    // ---- join ----
    cudaStreamWaitEvent(0, ev1, 0);

    // aggregate layer 1 (+bias, +BN1 stats+params) -> fp16 a1; single wave (148*6)
    agg128_kernel<<<888, 256>>>(b1, gamma1, beta1, N, invN);
    // h2 = (relu(bn1(a1)) @ W2) * dinv -> fp16
    mmagemm_kernel<64, true, false, true><<<gblk, 256, SMEM2>>>(nullptr, W2, N);
    // aggregate layer 2 into d_out (+BN2 stats+params+apply); single wave (148*4)
    agg64_kernel<<<592, 256>>>(b2, gamma2, beta2, out, N, invN);
}

// round 16
// speedup vs baseline: 1.2906x; 1.1003x over previous
#include <cuda_runtime.h>
#include <cuda_bf16.h>
#include <cuda_fp16.h>
#include <cstdint>

#define NMAX 100000
#define EMAX 1600000
#define INC  128
#define HID  128
#define OUTC 64
#define EPS  1e-5f

// ---------------- scratch (no allocations; all zero-init at module load,
// and each replay restores the zeros it consumed) ----------------
__device__ int    g_cnt[NMAX];
__device__ int    g_rowptr[NMAX + 1];
__device__ int    g_fill[NMAX];
__device__ int    g_col[EMAX];
__device__ float  g_dinv[NMAX];
__device__ int    g_bsum[128];
__device__ int    g_ctr1, g_ctr2, g_flag2, g_ctr3;
__device__ int    g_sbar, g_sflag, g_sdone;
__device__ __half g_h1h[(size_t)NMAX * HID];   // (x@W1)*dinv[row], fp16
__device__ __half g_a1h[(size_t)NMAX * HID];   // aggregated layer-1 (pre-BN), fp16
__device__ __half g_h2h[(size_t)NMAX * OUTC];  // (relu(bn1)@W2)*dinv[row], fp16
__device__ float  g_stats1[4 * HID];           // sum | sq | s | t
__device__ float  g_stats2[4 * OUTC];

// ---------------- helpers ----------------
__device__ __forceinline__ uint32_t smem_u32(const void* p) {
    uint32_t a;
    asm("{ .reg .u64 t; cvta.to.shared.u64 t, %1; cvt.u32.u64 %0, t; }" : "=r"(a) : "l"(p));
    return a;
}
__device__ __forceinline__ void ldmatrix_x4(uint32_t* r, uint32_t addr) {
    asm volatile("ldmatrix.sync.aligned.m8n8.x4.shared.b16 {%0,%1,%2,%3}, [%4];"
                 : "=r"(r[0]), "=r"(r[1]), "=r"(r[2]), "=r"(r[3]) : "r"(addr));
}
__device__ __forceinline__ void mma_f16(float* c, const uint32_t* a, uint32_t b0, uint32_t b1) {
    asm volatile(
        "mma.sync.aligned.m16n8k16.row.col.f32.f16.f16.f32 "
        "{%0,%1,%2,%3}, {%4,%5,%6,%7}, {%8,%9}, {%0,%1,%2,%3};"
        : "+f"(c[0]), "+f"(c[1]), "+f"(c[2]), "+f"(c[3])
        : "r"(a[0]), "r"(a[1]), "r"(a[2]), "r"(a[3]), "r"(b0), "r"(b1));
}

// ---------------- degree count: int4, 4 edges/thread ----------------
__global__ void count_kernel(const int* __restrict__ dst, int E) {
    int E4 = E >> 2;
    int i = blockIdx.x * blockDim.x + threadIdx.x;
    if (i < E4) {
        int4 d = ((const int4*)dst)[i];
        atomicAdd(&g_cnt[d.x], 1);
        atomicAdd(&g_cnt[d.y], 1);
        atomicAdd(&g_cnt[d.z], 1);
        atomicAdd(&g_cnt[d.w], 1);
    }
    int tbase = E4 << 2;
    int ti = tbase + i;
    if (i < (E - tbase)) atomicAdd(&g_cnt[dst[ti]], 1);
}

// ---------------- merged scan (both passes, self-resetting grid barrier) ----------------
__global__ __launch_bounds__(1024)
void scan_kernel(int n, int nb) {
    __shared__ int ws[32];
    int tid = threadIdx.x, lane = tid & 31, w = tid >> 5;
    int i = blockIdx.x * 1024 + tid;
    int v = (i < n) ? g_cnt[i] : 0;
    int x = v;
    #pragma unroll
    for (int off = 1; off < 32; off <<= 1) {
        int y = __shfl_up_sync(0xffffffffu, x, off);
        if (lane >= off) x += y;
    }
    if (lane == 31) ws[w] = x;
    __syncthreads();
    if (w == 0) {
        int y = ws[lane];
        #pragma unroll
        for (int off = 1; off < 32; off <<= 1) {
            int z = __shfl_up_sync(0xffffffffu, y, off);
            if (lane >= off) y += z;
        }
        ws[lane] = y;
    }
    __syncthreads();
    int incl = x + (w ? ws[w - 1] : 0);
    if (i < n) g_fill[i] = incl - v;
    if (tid == 1023) g_bsum[blockIdx.x] = incl;
    // grid barrier (98 blocks, all resident)
    __threadfence();
    __syncthreads();
    if (tid == 0) {
        if (atomicAdd(&g_sbar, 1) == (int)gridDim.x - 1) atomicExch(&g_sflag, 1);
        else while (atomicAdd(&g_sflag, 0) == 0) { }
    }
    __syncthreads();
    __threadfence();
    // pass 2: redundant scan of block sums + finalize
    __shared__ int excl[128];
    __shared__ int wsum[4];
    int xv = 0, vv = 0;
    if (tid < 128) {
        vv = (tid < nb) ? g_bsum[tid] : 0;
        xv = vv;
        #pragma unroll
        for (int off = 1; off < 32; off <<= 1) {
            int y = __shfl_up_sync(0xffffffffu, xv, off);
            if (lane >= off) xv += y;
        }
        if (lane == 31) wsum[w] = xv;
    }
    __syncthreads();
    if (tid < 128) {
        int add = 0;
        #pragma unroll
        for (int j = 0; j < 4; j++) if (j < w) add += wsum[j];
        excl[tid] = xv - vv + add;
    }
    __syncthreads();
    int off = excl[blockIdx.x];
    if (i < n) {
        int c = g_cnt[i];
        int ex = g_fill[i] + off;
        g_fill[i] = ex;
        g_rowptr[i + 1] = ex + c;
        g_dinv[i] = rsqrtf((float)(c + 1));
        if (i == 0) g_rowptr[0] = 0;
    }
    // completion: last block resets the barrier slots for next replay
    __threadfence();
    __syncthreads();
    if (tid == 0) {
        if (atomicAdd(&g_sdone, 1) == (int)gridDim.x - 1) {
            g_sbar = 0; g_sflag = 0; g_sdone = 0;
        }
    }
}

// ---------------- CSR fill: int4, 4 edges/thread ----------------
__global__ void fill_kernel(const int* __restrict__ src, const int* __restrict__ dst, int E) {
    int E4 = E >> 2;
    int i = blockIdx.x * blockDim.x + threadIdx.x;
    if (i < E4) {
        int4 d = ((const int4*)dst)[i];
        int4 s = ((const int4*)src)[i];
        int p0 = atomicAdd(&g_fill[d.x], 1);
        int p1 = atomicAdd(&g_fill[d.y], 1);
        int p2 = atomicAdd(&g_fill[d.z], 1);
        int p3 = atomicAdd(&g_fill[d.w], 1);
        g_col[p0] = s.x;
        g_col[p1] = s.y;
        g_col[p2] = s.z;
        g_col[p3] = s.w;
    }
    int tbase = E4 << 2;
    int ti = tbase + i;
    if (i < (E - tbase)) {
        int pos = atomicAdd(&g_fill[dst[ti]], 1);
        g_col[pos] = src[ti];
    }
}

// ---------------- HMMA fp16 GEMM: 2-term split (Ah*W + Al*W), fp32 accum ----------------
#define ASTR 136
template <int TN, bool PRE_BN, bool DINVC, bool DINV>
__global__ __launch_bounds__(256)
void mmagemm_kernel(const float* __restrict__ Aext, const float* __restrict__ W, int M) {
    extern __shared__ char smem[];
    const uint32_t SM_ST = 0;
    const uint32_t A_HI  = 1024;
    const uint32_t A_LO  = A_HI + 128 * ASTR * 2;
    const uint32_t B_    = A_LO + 128 * ASTR * 2;

    uint32_t sb = smem_u32(smem);
    int tid = threadIdx.x, wid = tid >> 5, lane = tid & 31;
    int m0 = blockIdx.x * 128;

    if (PRE_BN && tid < 256) {
        float v = (tid < 128) ? g_stats1[2 * HID + tid] : g_stats1[3 * HID + (tid - 128)];
        *(float*)(smem + SM_ST + tid * 4) = v;
    }

    __half* Cout = PRE_BN ? g_h2h : g_h1h;
    const float* s = (const float*)(smem + SM_ST);
    const float* t = s + 128;
    if (PRE_BN) __syncthreads();

    if (PRE_BN) {
        #pragma unroll
        for (int it = 0; it < 8; ++it) {
            int idx = tid + it * 256;
            int row = idx >> 4;
            int c8  = (idx & 15) * 8;
            uint4 u = make_uint4(0, 0, 0, 0);
            if (m0 + row < M) u = *(const uint4*)&g_a1h[(size_t)(m0 + row) * 128 + c8];
            const __half2* hp = (const __half2*)&u;
            uint32_t off = (uint32_t)row * (ASTR * 2) + (uint32_t)c8 * 2;
            #pragma unroll
            for (int j = 0; j < 4; j++) {
                float2 f = __half22float2(hp[j]);
                int k = c8 + 2 * j;
                f.x = fmaxf(fmaf(f.x, s[k + 0], t[k + 0]), 0.f);
                f.y = fmaxf(fmaf(f.y, s[k + 1], t[k + 1]), 0.f);
                __half2 h = __floats2half2_rn(f.x, f.y);
                float2 hf = __half22float2(h);
                __half2 l = __floats2half2_rn(f.x - hf.x, f.y - hf.y);
                *(__half2*)(smem + A_HI + off + 4 * j) = h;
                *(__half2*)(smem + A_LO + off + 4 * j) = l;
            }
        }
    } else {
        #pragma unroll
        for (int it = 0; it < 16; ++it) {
            int idx = tid + it * 256;
            int row = idx >> 5;
            int col = (idx & 31) << 2;
            float4 v = make_float4(0.f, 0.f, 0.f, 0.f);
            if (m0 + row < M) v = *(const float4*)&Aext[(size_t)(m0 + row) * 128 + col];
            __half2 h01 = __floats2half2_rn(v.x, v.y);
            __half2 h23 = __floats2half2_rn(v.z, v.w);
            float2 f01 = __half22float2(h01);
            float2 f23 = __half22float2(h23);
            __half2 l01 = __floats2half2_rn(v.x - f01.x, v.y - f01.y);
            __half2 l23 = __floats2half2_rn(v.z - f23.x, v.w - f23.y);
            uint32_t off = (uint32_t)row * (ASTR * 2) + (uint32_t)col * 2;
            *(__half2*)(smem + A_HI + off)     = h01;
            *(__half2*)(smem + A_HI + off + 4) = h23;
            *(__half2*)(smem + A_LO + off)     = l01;
            *(__half2*)(smem + A_LO + off + 4) = l23;
        }
    }
    // B: W [128, TN] row-major -> Wt[n][k] fp16 (single precision level)
    for (int idx = tid; idx < 128 * TN; idx += 256) {
        int k = idx / TN, n = idx % TN;
        uint32_t off = (uint32_t)n * (ASTR * 2) + (uint32_t)k * 2;
        *(__half*)(smem + B_ + off) = __float2half_rn(W[idx]);
    }
    __syncthreads();

    constexpr int WN   = TN / 2;
    constexpr int NSUB = WN / 8;
    int m_base = (wid & 3) * 32;
    int n_base = (wid >> 2) * WN;
    int g = lane >> 2, tt = lane & 3;

    float acc[2][NSUB][4];
    #pragma unroll
    for (int mi = 0; mi < 2; mi++)
        #pragma unroll
        for (int ni = 0; ni < NSUB; ni++)
            #pragma unroll
            for (int j = 0; j < 4; j++) acc[mi][ni][j] = 0.f;

    uint32_t a_row = (uint32_t)(m_base + (lane & 15));
    uint32_t a_cb  = (uint32_t)((lane >> 4) * 8);

    #pragma unroll
    for (int ks = 0; ks < 8; ++ks) {
        int k0 = ks * 16;
        uint32_t afh[2][4], afl[2][4];
        #pragma unroll
        for (int mi = 0; mi < 2; mi++) {
            uint32_t ro = (a_row + mi * 16) * (ASTR * 2) + (a_cb + k0) * 2;
            ldmatrix_x4(afh[mi], sb + A_HI + ro);
            ldmatrix_x4(afl[mi], sb + A_LO + ro);
        }
        const char* brow = smem + B_ + (uint32_t)(n_base + g) * (ASTR * 2) + (uint32_t)(k0 + 2 * tt) * 2;
        #pragma unroll
        for (int ni = 0; ni < NSUB; ni++) {
            uint32_t b0 = *(const uint32_t*)(brow + ni * 8 * (ASTR * 2));
            uint32_t b1 = *(const uint32_t*)(brow + ni * 8 * (ASTR * 2) + 16);
            mma_f16(acc[0][ni], afh[0], b0, b1);
            mma_f16(acc[0][ni], afl[0], b0, b1);
            mma_f16(acc[1][ni], afh[1], b0, b1);
            mma_f16(acc[1][ni], afl[1], b0, b1);
        }
    }

    #pragma unroll
    for (int mi = 0; mi < 2; mi++) {
        int r0 = m0 + m_base + mi * 16 + g;
        int r1 = r0 + 8;
        float d0 = 1.f, d1 = 1.f;
        if (DINVC) {
            d0 = (r0 < M) ? rsqrtf((float)(g_cnt[r0] + 1)) : 0.f;
            d1 = (r1 < M) ? rsqrtf((float)(g_cnt[r1] + 1)) : 0.f;
        }
        if (DINV) {
            d0 = (r0 < M) ? g_dinv[r0] : 0.f;
            d1 = (r1 < M) ? g_dinv[r1] : 0.f;
        }
        #pragma unroll
        for (int ni = 0; ni < NSUB; ni++) {
            int col = n_base + ni * 8 + 2 * tt;
            if (r0 < M)
                *(__half2*)&Cout[(size_t)r0 * TN + col] =
                    __floats2half2_rn(acc[mi][ni][0] * d0, acc[mi][ni][1] * d0);
            if (r1 < M)
                *(__half2*)&Cout[(size_t)r1 * TN + col] =
                    __floats2half2_rn(acc[mi][ni][2] * d1, acc[mi][ni][3] * d1);
        }
    }
}

// ---------------- aggregation helpers ----------------
__device__ __forceinline__ float4 h4_to_f4(uint2 u) {
    float2 a = __half22float2(*(__half2*)&u.x);
    float2 b = __half22float2(*(__half2*)&u.y);
    return make_float4(a.x, a.y, b.x, b.y);
}
__device__ __forceinline__ void acc4(float4& a, uint2 u) {
    float4 v = h4_to_f4(u);
    a.x += v.x; a.y += v.y; a.z += v.z; a.w += v.w;
}

// ---------------- aggregation, 128 cols; single wave; fused BN1 + state reset ----------------
__global__ __launch_bounds__(256, 6)
void agg128_kernel(const float* __restrict__ b, const float* __restrict__ gamma,
                   const float* __restrict__ beta, int n, float invN) {
    int gwarp  = (blockIdx.x * blockDim.x + threadIdx.x) >> 5;
    int lane   = threadIdx.x & 31;
    int nwarps = (gridDim.x * blockDim.x) >> 5;
    const uint2* __restrict__ base = (const uint2*)g_h1h;
    uint2* __restrict__ a1o = (uint2*)g_a1h;
    float4 bb = ((const float4*)b)[lane];
    float4 sum = make_float4(0, 0, 0, 0), sq = make_float4(0, 0, 0, 0);

    for (int node = gwarp; node < n; node += nwarps) {
        int e0 = g_rowptr[node], e1 = g_rowptr[node + 1];
        float4 acc = h4_to_f4(base[node * 32 + lane]);  // self-loop
        int e = e0;
        for (; e + 8 <= e1; e += 8) {
            int o0 = g_col[e]     * 32 + lane, o1 = g_col[e + 1] * 32 + lane;
            int o2 = g_col[e + 2] * 32 + lane, o3 = g_col[e + 3] * 32 + lane;
            int o4 = g_col[e + 4] * 32 + lane, o5 = g_col[e + 5] * 32 + lane;
            int o6 = g_col[e + 6] * 32 + lane, o7 = g_col[e + 7] * 32 + lane;
            uint2 v0 = base[o0];
            uint2 v1 = base[o1];
            uint2 v2 = base[o2];
            uint2 v3 = base[o3];
            uint2 v4 = base[o4];
            uint2 v5 = base[o5];
            uint2 v6 = base[o6];
            uint2 v7 = base[o7];
            acc4(acc, v0); acc4(acc, v1); acc4(acc, v2); acc4(acc, v3);
            acc4(acc, v4); acc4(acc, v5); acc4(acc, v6); acc4(acc, v7);
        }
        for (; e + 4 <= e1; e += 4) {
            int o0 = g_col[e]     * 32 + lane, o1 = g_col[e + 1] * 32 + lane;
            int o2 = g_col[e + 2] * 32 + lane, o3 = g_col[e + 3] * 32 + lane;
            uint2 v0 = base[o0];
            uint2 v1 = base[o1];
            uint2 v2 = base[o2];
            uint2 v3 = base[o3];
            acc4(acc, v0); acc4(acc, v1); acc4(acc, v2); acc4(acc, v3);
        }
        for (; e < e1; e++) acc4(acc, base[g_col[e] * 32 + lane]);
        float d = g_dinv[node];
        float4 o;
        o.x = fmaf(acc.x, d, bb.x); o.y = fmaf(acc.y, d, bb.y);
        o.z = fmaf(acc.z, d, bb.z); o.w = fmaf(acc.w, d, bb.w);
        uint2 st;
        *(__half2*)&st.x = __floats2half2_rn(o.x, o.y);
        *(__half2*)&st.y = __floats2half2_rn(o.z, o.w);
        a1o[node * 32 + lane] = st;
        sum.x += o.x; sum.y += o.y; sum.z += o.z; sum.w += o.w;
        sq.x += o.x * o.x; sq.y += o.y * o.y; sq.z += o.z * o.z; sq.w += o.w * o.w;
    }
    // distributed reset of g_cnt for next replay (g_cnt no longer needed: GEMM1 done)
    for (int i = blockIdx.x * blockDim.x + threadIdx.x; i < n; i += gridDim.x * blockDim.x)
        g_cnt[i] = 0;

    __shared__ float ssum[HID], ssq[HID];
    int t = threadIdx.x;
    if (t < HID) { ssum[t] = 0.f; ssq[t] = 0.f; }
    __syncthreads();
    int c0 = lane * 4;
    atomicAdd(&ssum[c0 + 0], sum.x); atomicAdd(&ssum[c0 + 1], sum.y);
    atomicAdd(&ssum[c0 + 2], sum.z); atomicAdd(&ssum[c0 + 3], sum.w);
    atomicAdd(&ssq[c0 + 0], sq.x);  atomicAdd(&ssq[c0 + 1], sq.y);
    atomicAdd(&ssq[c0 + 2], sq.z);  atomicAdd(&ssq[c0 + 3], sq.w);
    __syncthreads();
    if (t < HID) {
        atomicAdd(&g_stats1[t], ssum[t]);
        atomicAdd(&g_stats1[HID + t], ssq[t]);
    }
    __threadfence();
    __shared__ int isLast;
    __syncthreads();
    if (t == 0) isLast = (atomicAdd(&g_ctr1, 1) == (int)gridDim.x - 1);
    __syncthreads();
    if (isLast) {
        if (t < HID) {
            float mean = g_stats1[t] * invN;
            float var  = g_stats1[HID + t] * invN - mean * mean;
            float sc = gamma[t] * rsqrtf(var + EPS);
            g_stats1[2 * HID + t] = sc;
            g_stats1[3 * HID + t] = beta[t] - mean * sc;
        }
        __syncthreads();  // params computed before sums are cleared
        if (t < 2 * HID) g_stats1[t] = 0.f;   // reset sums for next replay
        if (t == 0) g_ctr1 = 0;
    }
}

// ---------------- aggregation, 64 cols; fused grid-barrier BN2 + state reset ----------------
__global__ __launch_bounds__(256, 4)
void agg64_kernel(const float* __restrict__ b, const float* __restrict__ gamma,
                  const float* __restrict__ beta, float* __restrict__ out,
                  int n, float invN) {
    int gwarp  = (blockIdx.x * blockDim.x + threadIdx.x) >> 5;
    int lane   = threadIdx.x & 31;
    int nwarps = (gridDim.x * blockDim.x) >> 5;
    const __half2* __restrict__ base = (const __half2*)g_h2h;
    float2 bb = ((const float2*)b)[lane];
    float2 sum = make_float2(0, 0), sq = make_float2(0, 0);

    for (int node = gwarp; node < n; node += nwarps) {
        int e0 = g_rowptr[node], e1 = g_rowptr[node + 1];
        float2 acc = __half22float2(base[node * 32 + lane]);
        int e = e0;
        for (; e + 8 <= e1; e += 8) {
            int o0 = g_col[e]     * 32 + lane, o1 = g_col[e + 1] * 32 + lane;
            int o2 = g_col[e + 2] * 32 + lane, o3 = g_col[e + 3] * 32 + lane;
            int o4 = g_col[e + 4] * 32 + lane, o5 = g_col[e + 5] * 32 + lane;
            int o6 = g_col[e + 6] * 32 + lane, o7 = g_col[e + 7] * 32 + lane;
            __half2 h0 = base[o0];
            __half2 h1 = base[o1];
            __half2 h2 = base[o2];
            __half2 h3 = base[o3];
            __half2 h4 = base[o4];
            __half2 h5 = base[o5];
            __half2 h6 = base[o6];
            __half2 h7 = base[o7];
            float2 f;
            f = __half22float2(h0); acc.x += f.x; acc.y += f.y;
            f = __half22float2(h1); acc.x += f.x; acc.y += f.y;
            f = __half22float2(h2); acc.x += f.x; acc.y += f.y;
            f = __half22float2(h3); acc.x += f.x; acc.y += f.y;
            f = __half22float2(h4); acc.x += f.x; acc.y += f.y;
            f = __half22float2(h5); acc.x += f.x; acc.y += f.y;
            f = __half22float2(h6); acc.x += f.x; acc.y += f.y;
            f = __half22float2(h7); acc.x += f.x; acc.y += f.y;
        }
        for (; e + 4 <= e1; e += 4) {
            int o0 = g_col[e]     * 32 + lane, o1 = g_col[e + 1] * 32 + lane;
            int o2 = g_col[e + 2] * 32 + lane, o3 = g_col[e + 3] * 32 + lane;
            float2 v0 = __half22float2(base[o0]);
            float2 v1 = __half22float2(base[o1]);
            float2 v2 = __half22float2(base[o2]);
            float2 v3 = __half22float2(base[o3]);
            acc.x += (v0.x + v1.x) + (v2.x + v3.x);
            acc.y += (v0.y + v1.y) + (v2.y + v3.y);
        }
        for (; e < e1; e++) {
            float2 v = __half22float2(base[g_col[e] * 32 + lane]);
            acc.x += v.x; acc.y += v.y;
        }
        float d = g_dinv[node];
        float2 o;
        o.x = fmaf(acc.x, d, bb.x); o.y = fmaf(acc.y, d, bb.y);
        ((float2*)out)[node * 32 + lane] = o;
        sum.x += o.x; sum.y += o.y;
        sq.x += o.x * o.x; sq.y += o.y * o.y;
    }
    __shared__ float ssum[OUTC], ssq[OUTC];
    __shared__ float sS[OUTC], sT[OUTC];
    int t = threadIdx.x;
    if (t < OUTC) { ssum[t] = 0.f; ssq[t] = 0.f; }
    __syncthreads();
    int c0 = lane * 2;
    atomicAdd(&ssum[c0 + 0], sum.x); atomicAdd(&ssum[c0 + 1], sum.y);
    atomicAdd(&ssq[c0 + 0], sq.x);  atomicAdd(&ssq[c0 + 1], sq.y);
    __syncthreads();
    if (t < OUTC) {
        atomicAdd(&g_stats2[t], ssum[t]);
        atomicAdd(&g_stats2[OUTC + t], ssq[t]);
    }
    __threadfence();
    __shared__ int isLast;
    __syncthreads();
    if (t == 0) isLast = (atomicAdd(&g_ctr2, 1) == (int)gridDim.x - 1);
    __syncthreads();
    if (isLast) {
        if (t < OUTC) {
            float mean = g_stats2[t] * invN;
            float var  = g_stats2[OUTC + t] * invN - mean * mean;
            float sc = gamma[t] * rsqrtf(var + EPS);
            g_stats2[2 * OUTC + t] = sc;
            g_stats2[3 * OUTC + t] = beta[t] - mean * sc;
        }
        __threadfence();
        __syncthreads();
        if (t == 0) atomicExch(&g_flag2, 1);
    }
    if (t == 0) { while (atomicAdd(&g_flag2, 0) == 0) { } }
    __syncthreads();
    if (t < OUTC) { sS[t] = g_stats2[2 * OUTC + t]; sT[t] = g_stats2[3 * OUTC + t]; }
    __syncthreads();
    int gtid = blockIdx.x * blockDim.x + t;
    int stride = gridDim.x * blockDim.x;
    int total4 = n * (OUTC / 4);
    float4* o4 = (float4*)out;
    for (int i = gtid; i < total4; i += stride) {
        float4 v = o4[i];
        int c = (i & 15) * 4;
        v.x = fmaf(v.x, sS[c + 0], sT[c + 0]);
        v.y = fmaf(v.y, sS[c + 1], sT[c + 1]);
        v.z = fmaf(v.z, sS[c + 2], sT[c + 2]);
        v.w = fmaf(v.w, sS[c + 3], sT[c + 3]);
        o4[i] = v;
    }
    // completion counter: last block to finish resets barrier state + stats sums
    __threadfence();
    __syncthreads();
    if (t == 0) {
        if (atomicAdd(&g_ctr3, 1) == (int)gridDim.x - 1) {
            for (int i = 0; i < 2 * OUTC; i++) g_stats2[i] = 0.f;
            g_ctr2 = 0; g_flag2 = 0; g_ctr3 = 0;
        }
    }
}

extern "C" void kernel_launch(void* const* d_in, const int* in_sizes, int n_in,
                              void* d_out, int out_size) {
    const float* x      = (const float*)d_in[0];
    const float* W1     = (const float*)d_in[1];
    const float* b1     = (const float*)d_in[2];
    const float* gamma1 = (const float*)d_in[3];
    const float* beta1  = (const float*)d_in[4];
    const float* W2     = (const float*)d_in[5];
    const float* b2     = (const float*)d_in[6];
    const float* gamma2 = (const float*)d_in[7];
    const float* beta2  = (const float*)d_in[8];
    const int*   ei     = (const int*)d_in[9];
    float*       out    = (float*)d_out;

    int N = in_sizes[0] / INC;     // 100000
    int E = in_sizes[9] / 2;       // 1600000
    const int* src = ei;
    const int* dst = ei + E;
    float invN = 1.0f / (float)N;

    // smem: BN s/t + A hi/lo (2*34816) + B (TN*272)
    const int SMEM1 = 1024 + 2 * 128 * ASTR * 2 + 128 * ASTR * 2;  // 105472
    const int SMEM2 = 1024 + 2 * 128 * ASTR * 2 + 64 * ASTR * 2;   // 88064

    static cudaStream_t s2 = nullptr;
    static cudaEvent_t  evC = nullptr, ev1 = nullptr;
    if (!s2) {
        cudaFuncSetAttribute(mmagemm_kernel<128, false, true, false>,
                             cudaFuncAttributeMaxDynamicSharedMemorySize, SMEM1);
        cudaFuncSetAttribute(mmagemm_kernel<64, true, false, true>,
                             cudaFuncAttributeMaxDynamicSharedMemorySize, SMEM2);
        cudaStreamCreateWithFlags(&s2, cudaStreamNonBlocking);
        cudaEventCreateWithFlags(&evC, cudaEventDisableTiming);
        cudaEventCreateWithFlags(&ev1, cudaEventDisableTiming);
    }

    int nb = (N + 1023) / 1024;   // 98
    int gblk = (N + 127) / 128;
    int e4blk = (E / 4 + 255) / 256;

    // ---- main: degree counts (g_cnt is zero from module-load / previous replay) ----
    count_kernel<<<e4blk, 256>>>(dst, E);
    cudaEventRecord(evC, 0);

    // ---- side: GEMM1 with dinv folded from counts ----
    cudaStreamWaitEvent(s2, evC, 0);
    mmagemm_kernel<128, false, true, false><<<gblk, 256, SMEM1, s2>>>(x, W1, N);
    cudaEventRecord(ev1, s2);

    // ---- main: merged scan + fill (overlaps GEMM1) ----
    scan_kernel<<<nb, 1024>>>(N, nb);
    fill_kernel<<<e4blk, 256>>>(src, dst, E);

    // ---- join ----
    cudaStreamWaitEvent(0, ev1, 0);

    // aggregate layer 1 (+bias, +BN1 stats+params, +g_cnt/stats reset); single wave
    agg128_kernel<<<888, 256>>>(b1, gamma1, beta1, N, invN);
    // h2 = (relu(bn1(a1)) @ W2) * dinv -> fp16
    mmagemm_kernel<64, true, false, true><<<gblk, 256, SMEM2>>>(nullptr, W2, N);
    // aggregate layer 2 into d_out (+BN2 stats+params+apply, +state reset); single wave
    agg64_kernel<<<592, 256>>>(b2, gamma2, beta2, out, N, invN);
}